// round 14
// baseline (speedup 1.0000x reference)
#include <cuda_runtime.h>
#include <cuda_bf16.h>
#include <cstddef>
#include <cstdint>

// Problem constants
#define BB    4
#define TSEQ  2048
#define CDIM  2048
#define MTOT  8192          // BB*TSEQ
#define HHEADS 32
#define NSZ   64
#define GN_EPS 6.4e-4f      // 1e-5 * 8^2

// ---------------------------------------------------------------------------
// Scratch
// ---------------------------------------------------------------------------
__device__ float g_apack[4ull * MTOT * CDIM];   // fragment-packed tf32: xk,xv,xr,xg
__device__ float g_ypack[(size_t)MTOT * CDIM];  // fragment-packed gn*gate
__device__ float g_wpack[5ull * CDIM * CDIM];   // fragment-packed weights: r,k,v,g,o
__device__ float g_xd  [(size_t)MTOT * CDIM];
__device__ float g_t5  [MTOT * 160];
__device__ float g_r   [(size_t)MTOT * CDIM];
__device__ float g_k   [(size_t)MTOT * CDIM];
__device__ float g_v   [(size_t)MTOT * CDIM];
__device__ float g_gt  [(size_t)MTOT * CDIM];
__device__ float g_w   [(size_t)MTOT * CDIM];
__device__ float g_h   [MTOT * 64];
__device__ float g_a   [(size_t)MTOT * CDIM];

// ---------------------------------------------------------------------------
// side streams + events for graph-captured fork/join
// ---------------------------------------------------------------------------
struct StreamEnv {
    cudaStream_t s1 = nullptr, s2 = nullptr;
    cudaEvent_t evRoot = nullptr, ePack = nullptr, eLerp = nullptr;
    cudaEvent_t eDecay = nullptr, eRKV = nullptr, eGate = nullptr;
    StreamEnv() {
        cudaStreamCreateWithFlags(&s1, cudaStreamNonBlocking);
        cudaStreamCreateWithFlags(&s2, cudaStreamNonBlocking);
        cudaEventCreateWithFlags(&evRoot, cudaEventDisableTiming);
        cudaEventCreateWithFlags(&ePack, cudaEventDisableTiming);
        cudaEventCreateWithFlags(&eLerp, cudaEventDisableTiming);
        cudaEventCreateWithFlags(&eDecay, cudaEventDisableTiming);
        cudaEventCreateWithFlags(&eRKV, cudaEventDisableTiming);
        cudaEventCreateWithFlags(&eGate, cudaEventDisableTiming);
    }
};
static StreamEnv g_env;

// ---------------------------------------------------------------------------
// helpers
// ---------------------------------------------------------------------------
__device__ __forceinline__ unsigned long long f2_pack(float lo, float hi) {
    unsigned long long r;
    asm("mov.b64 %0, {%1, %2};" : "=l"(r) : "f"(lo), "f"(hi));
    return r;
}
__device__ __forceinline__ void f2_unpack(unsigned long long v, float& lo, float& hi) {
    asm("mov.b64 {%0, %1}, %2;" : "=f"(lo), "=f"(hi) : "l"(v));
}
__device__ __forceinline__ unsigned long long f2_fma(unsigned long long a,
                                                     unsigned long long b,
                                                     unsigned long long c) {
    unsigned long long d;
    asm("fma.rn.f32x2 %0, %1, %2, %3;" : "=l"(d) : "l"(a), "l"(b), "l"(c));
    return d;
}
__device__ __forceinline__ unsigned long long f2_mul(unsigned long long a,
                                                     unsigned long long b) {
    unsigned long long d;
    asm("mul.rn.f32x2 %0, %1, %2;" : "=l"(d) : "l"(a), "l"(b));
    return d;
}
__device__ __forceinline__ float tf32r(float x) {
    uint32_t u;
    asm("cvt.rna.tf32.f32 %0, %1;" : "=r"(u) : "f"(x));
    return __uint_as_float(u);
}
__device__ __forceinline__ uint32_t su32(const void* p) {
    uint32_t a;
    asm("{ .reg .u64 t; cvta.to.shared.u64 t, %1; cvt.u32.u64 %0, t; }" : "=r"(a) : "l"(p));
    return a;
}
__device__ __forceinline__ void cp16(uint32_t dst, const void* src) {
    asm volatile("cp.async.cg.shared.global [%0], [%1], 16;" :: "r"(dst), "l"(src));
}
__device__ __forceinline__ void cp4(uint32_t dst, const void* src) {
    asm volatile("cp.async.ca.shared.global [%0], [%1], 4;" :: "r"(dst), "l"(src));
}
#define CP_COMMIT() asm volatile("cp.async.commit_group;" ::: "memory")
#define CP_WAIT1()  asm volatile("cp.async.wait_group 1;" ::: "memory")
#define CP_WAIT6()  asm volatile("cp.async.wait_group 6;" ::: "memory")

__device__ __forceinline__ void mma8(float* c, const uint32_t* a, const uint32_t* b) {
    asm volatile(
        "mma.sync.aligned.m16n8k8.row.col.f32.tf32.tf32.f32 "
        "{%0,%1,%2,%3}, {%4,%5,%6,%7}, {%8,%9}, {%0,%1,%2,%3};"
        : "+f"(c[0]), "+f"(c[1]), "+f"(c[2]), "+f"(c[3])
        : "r"(a[0]), "r"(a[1]), "r"(a[2]), "r"(a[3]), "r"(b[0]), "r"(b[1]));
}

// -------- fragment-packed global layouts --------
__device__ __forceinline__ size_t packA_idx(int m, int k) {
    int r = m & 15, c = k & 7;
    int lane = ((r & 7) << 2) | (c & 3);
    int i = (r >> 3) | ((c >> 2) << 1);
    int atom = (((m >> 4) & 7) << 2) | ((k >> 3) & 3);
    size_t tile = ((size_t)(m >> 7) << 6) + (size_t)(k >> 5);
    return (tile << 12) + (size_t)((atom << 7) + (lane << 2) + i);
}
__device__ __forceinline__ size_t packB_idx(int n, int k) {
    int lane = ((n & 7) << 2) | (k & 3);
    int j = (k >> 2) & 1;
    int atom = (((n >> 3) & 31) << 2) | ((k >> 3) & 3);
    size_t tile = ((size_t)(n >> 8) << 6) + (size_t)(k >> 5);
    return (tile << 13) + (size_t)((atom << 6) + (lane << 1) + j);
}

// ---------------------------------------------------------------------------
// pack all 5 weights
// ---------------------------------------------------------------------------
__global__ __launch_bounds__(256) void k_packB_all(const float* __restrict__ w0,
                                                   const float* __restrict__ w1,
                                                   const float* __restrict__ w2,
                                                   const float* __restrict__ w3,
                                                   const float* __restrict__ w4,
                                                   float* __restrict__ o)
{
    const float* ws[5] = {w0, w1, w2, w3, w4};
    const float* w = ws[blockIdx.y];
    float* oo = o + (size_t)blockIdx.y * CDIM * CDIM;
    int g = blockIdx.x * 256 + threadIdx.x;
    int n = g >> 11, k = g & 2047;
    oo[packB_idx(n, k)] = tf32r(w[g]);
}

// ---------------------------------------------------------------------------
// t5 = tanh( (x + (shift(x)-x)*maa_x) @ W1 )   [M,160]
// ---------------------------------------------------------------------------
__global__ __launch_bounds__(256) void k_prep_t5(const float* __restrict__ x,
                                                 const float* __restrict__ maa_x,
                                                 const float* __restrict__ w1)
{
    __shared__ float As[64][33];
    __shared__ float Bs[32][160];
    const int tid = threadIdx.x;
    const int row0 = blockIdx.x * 64;
    const int tx = tid & 31, ty = tid >> 5;
    const int col0 = tx * 5, r0 = ty * 8;

    float acc[8][5];
#pragma unroll
    for (int i = 0; i < 8; i++)
#pragma unroll
        for (int j = 0; j < 5; j++) acc[i][j] = 0.f;

    for (int k0 = 0; k0 < CDIM; k0 += 32) {
        __syncthreads();
#pragma unroll
        for (int i = 0; i < 8; i++) {
            int lin = i * 256 + tid;
            int r = lin >> 5, kk = lin & 31;
            int gr = row0 + r, gc = k0 + kk;
            float xv = x[(size_t)gr * CDIM + gc];
            float xp = (gr & (TSEQ - 1)) ? x[(size_t)(gr - 1) * CDIM + gc] : 0.f;
            As[r][kk] = xv + (xp - xv) * maa_x[gc];
        }
#pragma unroll
        for (int i = 0; i < 20; i++) {
            int lin = i * 256 + tid;
            int kk = lin / 160, c = lin - kk * 160;
            Bs[kk][c] = w1[(size_t)(k0 + kk) * 160 + c];
        }
        __syncthreads();
#pragma unroll
        for (int kk = 0; kk < 32; kk++) {
            float a[8], b[5];
#pragma unroll
            for (int i = 0; i < 8; i++) a[i] = As[r0 + i][kk];
#pragma unroll
            for (int j = 0; j < 5; j++) b[j] = Bs[kk][col0 + j];
#pragma unroll
            for (int i = 0; i < 8; i++)
#pragma unroll
                for (int j = 0; j < 5; j++)
                    acc[i][j] = fmaf(a[i], b[j], acc[i][j]);
        }
    }
#pragma unroll
    for (int i = 0; i < 8; i++)
#pragma unroll
        for (int j = 0; j < 5; j++)
            g_t5[(size_t)(row0 + r0 + i) * 160 + col0 + j] = tanhf(acc[i][j]);
}

// ---------------------------------------------------------------------------
// for f in 0..4: lerp_f = x + xx*(maa_f + t5[:,f,:] @ w2[f])   (R5 version)
// ---------------------------------------------------------------------------
__global__ __launch_bounds__(256) void k_lerp5(const float* __restrict__ x,
                                               const float* __restrict__ w2,
                                               const float* __restrict__ maa_w,
                                               const float* __restrict__ maa_k,
                                               const float* __restrict__ maa_v,
                                               const float* __restrict__ maa_r,
                                               const float* __restrict__ maa_g)
{
    __shared__ float t5s[16][160];
    __shared__ float w2s[32][256];
    const int tid = threadIdx.x;
    const int ct = blockIdx.x & 7;
    const int rt = blockIdx.x >> 3;
    const int row0 = rt * 16;
    const int c = ct * 256 + tid;
    const size_t MC = (size_t)MTOT * CDIM;

#pragma unroll
    for (int i = 0; i < 10; i++) {
        int lin = i * 256 + tid;
        int r = lin / 160, e = lin - r * 160;
        t5s[r][e] = g_t5[(size_t)(row0 + r) * 160 + e];
    }
    float xv[16], xxv[16];
#pragma unroll
    for (int r = 0; r < 16; r++) {
        int gr = row0 + r;
        float v = x[(size_t)gr * CDIM + c];
        float p = (gr & (TSEQ - 1)) ? x[(size_t)(gr - 1) * CDIM + c] : 0.f;
        xv[r] = v; xxv[r] = p - v;
    }
    const float* maas[5] = {maa_w, maa_k, maa_v, maa_r, maa_g};

    for (int f = 0; f < 5; f++) {
        __syncthreads();
#pragma unroll
        for (int e = 0; e < 32; e++)
            w2s[e][tid] = w2[(size_t)(f * 32 + e) * CDIM + c];
        __syncthreads();

        float acc[16];
#pragma unroll
        for (int r = 0; r < 16; r++) acc[r] = 0.f;
#pragma unroll
        for (int e = 0; e < 32; e++) {
            float we = w2s[e][tid];
#pragma unroll
            for (int r = 0; r < 16; r++)
                acc[r] = fmaf(t5s[r][f * 32 + e], we, acc[r]);
        }
        float mb = maas[f][c];
        if (f == 0) {
#pragma unroll
            for (int r = 0; r < 16; r++)
                g_xd[(size_t)(row0 + r) * CDIM + c] = xv[r] + xxv[r] * (mb + acc[r]);
        } else {
            float* outp = g_apack + (size_t)(f - 1) * MC;
#pragma unroll
            for (int r = 0; r < 16; r++)
                outp[packA_idx(row0 + r, c)] = tf32r(xv[r] + xxv[r] * (mb + acc[r]));
        }
    }
}

// ---------------------------------------------------------------------------
// tf32 mma.sync GEMM body (R11 known-best)
// ---------------------------------------------------------------------------
__device__ __forceinline__ void gemm_body(const float* __restrict__ Ap,
                                          const float* __restrict__ Bp,
                                          float* __restrict__ Co,
                                          int bx, int by, bool silu,
                                          float* sm)
{
    const int tid = threadIdx.x;
    const int lane = tid & 31, wid = tid >> 5;
    const int warp_m = wid >> 1, warp_n = wid & 1;

    const float* Ag = Ap + ((size_t)by << 6 << 12);
    const float* Bg = Bp + ((size_t)(bx >> 1) << 6 << 13)
                         + (size_t)(bx & 1) * 4096;
    const uint32_t sbase = su32(sm);

    float c[4][8][4];
#pragma unroll
    for (int fm = 0; fm < 4; fm++)
#pragma unroll
        for (int fn = 0; fn < 8; fn++)
#pragma unroll
            for (int i = 0; i < 4; i++) c[fm][fn][i] = 0.f;

#define ISSUE(kt)                                                                  \
    do {                                                                           \
        uint32_t d = sbase + ((kt) % 3) * 32768;                                   \
        const float4* a4 = (const float4*)(Ag + ((size_t)(kt) << 12));             \
        const float4* b4 = (const float4*)(Bg + ((size_t)(kt) << 13));             \
        _Pragma("unroll")                                                          \
        for (int i = 0; i < 8; i++)                                                \
            cp16(d + (uint32_t)(tid + i * 128) * 16, a4 + tid + i * 128);          \
        _Pragma("unroll")                                                          \
        for (int i = 0; i < 8; i++)                                                \
            cp16(d + 16384 + (uint32_t)(tid + i * 128) * 16, b4 + tid + i * 128);  \
    } while (0)

#define LOAD_FRAG(ks, abuf, bbuf)                                                   \
    do {                                                                            \
        _Pragma("unroll")                                                           \
        for (int fm = 0; fm < 4; fm++) {                                            \
            const uint4* p = (const uint4*)As + (((warp_m * 4 + fm) * 4 + (ks)) * 32 + lane); \
            uint4 v = *p;                                                           \
            (abuf)[fm][0] = v.x; (abuf)[fm][1] = v.y;                               \
            (abuf)[fm][2] = v.z; (abuf)[fm][3] = v.w;                               \
        }                                                                           \
        _Pragma("unroll")                                                           \
        for (int fn = 0; fn < 8; fn++) {                                            \
            const uint2* p = (const uint2*)Bs + (((warp_n * 8 + fn) * 4 + (ks)) * 32 + lane); \
            uint2 v = *p;                                                           \
            (bbuf)[fn][0] = v.x; (bbuf)[fn][1] = v.y;                               \
        }                                                                           \
    } while (0)

    ISSUE(0); CP_COMMIT();
    ISSUE(1); CP_COMMIT();

    uint32_t a[2][4][4], b[2][8][2];

    for (int kt = 0; kt < 64; kt++) {
        CP_WAIT1();
        __syncthreads();
        if (kt + 2 < 64) ISSUE(kt + 2);
        CP_COMMIT();

        const float* As = sm + (kt % 3) * 8192;
        const float* Bs = As + 4096;

        LOAD_FRAG(0, a[0], b[0]);
#pragma unroll
        for (int ks = 0; ks < 4; ks++) {
            const int cur = ks & 1;
            if (ks < 3) LOAD_FRAG(ks + 1, a[cur ^ 1], b[cur ^ 1]);
#pragma unroll
            for (int fm = 0; fm < 4; fm++)
#pragma unroll
                for (int fn = 0; fn < 8; fn++)
                    mma8(c[fm][fn], a[cur][fm], b[cur][fn]);
        }
    }
#undef ISSUE
#undef LOAD_FRAG

    const int r0 = by * 128 + warp_m * 64 + (lane >> 2);
    const int c0 = bx * 128 + warp_n * 64 + (lane & 3) * 2;
#pragma unroll
    for (int fm = 0; fm < 4; fm++) {
#pragma unroll
        for (int fn = 0; fn < 8; fn++) {
            int row = r0 + fm * 16;
            int col = c0 + fn * 8;
            float2 v0 = make_float2(c[fm][fn][0], c[fm][fn][1]);
            float2 v1 = make_float2(c[fm][fn][2], c[fm][fn][3]);
            if (silu) {
                v0.x = v0.x / (1.f + expf(-v0.x));
                v0.y = v0.y / (1.f + expf(-v0.y));
                v1.x = v1.x / (1.f + expf(-v1.x));
                v1.y = v1.y / (1.f + expf(-v1.y));
            }
            *(float2*)(Co + (size_t)row * CDIM + col) = v0;
            *(float2*)(Co + (size_t)(row + 8) * CDIM + col) = v1;
        }
    }
}

// r,k,v projections: blockIdx.z in {0,1,2}
__global__ __launch_bounds__(128) void k_gemm_rkv(const float* __restrict__ Abase,
                                                  const float* __restrict__ Wbase,
                                                  float* __restrict__ o_r,
                                                  float* __restrict__ o_k,
                                                  float* __restrict__ o_v)
{
    extern __shared__ __align__(16) float sm[];
    const int z = blockIdx.z;
    const size_t MC = (size_t)MTOT * CDIM;
    const size_t WSLOT = (size_t)CDIM * CDIM;
    const int aslot = (z == 0) ? 2 : (z == 1) ? 0 : 1;
    float* Co = (z == 0) ? o_r : (z == 1) ? o_k : o_v;
    gemm_body(Abase + (size_t)aslot * MC, Wbase + (size_t)z * WSLOT, Co,
              blockIdx.x, blockIdx.y, false, sm);
}

// gate projection (silu) — runs concurrent with wkv
__global__ __launch_bounds__(128) void k_gemm_g(const float* __restrict__ Ap,
                                                const float* __restrict__ Bp,
                                                float* __restrict__ Co)
{
    extern __shared__ __align__(16) float sm[];
    gemm_body(Ap, Bp, Co, blockIdx.x, blockIdx.y, true, sm);
}

// single GEMM (output projection)
__global__ __launch_bounds__(128) void k_gemm1(const float* __restrict__ Ap,
                                               const float* __restrict__ Bp,
                                               float* __restrict__ Co)
{
    extern __shared__ __align__(16) float sm[];
    gemm_body(Ap, Bp, Co, blockIdx.x, blockIdx.y, false, sm);
}

// ---------------------------------------------------------------------------
// h = tanh(xd @ dw1)  [M,64]
// ---------------------------------------------------------------------------
__global__ __launch_bounds__(256) void k_decay_h(const float* __restrict__ dw1)
{
    __shared__ float As[64][33];
    __shared__ float Bs[32][64];
    const int tid = threadIdx.x;
    const int row0 = blockIdx.x * 64;
    const int tx = tid & 15, ty = tid >> 4;
    const int col0 = tx * 4, r0 = ty * 4;

    float acc[4][4];
#pragma unroll
    for (int i = 0; i < 4; i++)
#pragma unroll
        for (int j = 0; j < 4; j++) acc[i][j] = 0.f;

    for (int k0 = 0; k0 < CDIM; k0 += 32) {
        __syncthreads();
#pragma unroll
        for (int i = 0; i < 8; i++) {
            int lin = i * 256 + tid;
            int r = lin >> 5, kk = lin & 31;
            As[r][kk] = g_xd[(size_t)(row0 + r) * CDIM + k0 + kk];
        }
#pragma unroll
        for (int i = 0; i < 8; i++) {
            int lin = i * 256 + tid;
            int kk = lin >> 6, cc = lin & 63;
            Bs[kk][cc] = dw1[(size_t)(k0 + kk) * 64 + cc];
        }
        __syncthreads();
#pragma unroll
        for (int kk = 0; kk < 32; kk++) {
            float a[4], b[4];
#pragma unroll
            for (int i = 0; i < 4; i++) a[i] = As[r0 + i][kk];
#pragma unroll
            for (int j = 0; j < 4; j++) b[j] = Bs[kk][col0 + j];
#pragma unroll
            for (int i = 0; i < 4; i++)
#pragma unroll
                for (int j = 0; j < 4; j++)
                    acc[i][j] = fmaf(a[i], b[j], acc[i][j]);
        }
    }
#pragma unroll
    for (int i = 0; i < 4; i++)
#pragma unroll
        for (int j = 0; j < 4; j++)
            g_h[(size_t)(row0 + r0 + i) * 64 + col0 + j] = tanhf(acc[i][j]);
}

// ---------------------------------------------------------------------------
// w = exp(-exp(time_decay + h @ dw2))  [M,C]
// ---------------------------------------------------------------------------
__global__ __launch_bounds__(256) void k_decay_w(const float* __restrict__ dw2,
                                                 const float* __restrict__ tdec)
{
    __shared__ float hs[16][64];
    __shared__ float ws[32][256];
    const int tid = threadIdx.x;
    const int ct = blockIdx.x & 7;
    const int rt = blockIdx.x >> 3;
    const int row0 = rt * 16;
    const int c = ct * 256 + tid;

#pragma unroll
    for (int i = 0; i < 4; i++) {
        int lin = i * 256 + tid;
        int r = lin >> 6, e = lin & 63;
        hs[r][e] = g_h[(size_t)(row0 + r) * 64 + e];
    }
    float acc[16];
#pragma unroll
    for (int r = 0; r < 16; r++) acc[r] = 0.f;

    for (int ch = 0; ch < 2; ch++) {
        __syncthreads();
#pragma unroll
        for (int e = 0; e < 32; e++)
            ws[e][tid] = dw2[(size_t)(ch * 32 + e) * CDIM + c];
        __syncthreads();
#pragma unroll
        for (int e = 0; e < 32; e++) {
            float we = ws[e][tid];
#pragma unroll
            for (int r = 0; r < 16; r++)
                acc[r] = fmaf(hs[r][ch * 32 + e], we, acc[r]);
        }
    }
    float tb = tdec[c];
#pragma unroll
    for (int r = 0; r < 16; r++)
        g_w[(size_t)(row0 + r) * CDIM + c] = expf(-expf(tb + acc[r]));
}

// ---------------------------------------------------------------------------
// WKV scan. One block per (b,h). 8-deep cp.async ring, prefetch distance 6.
// ---------------------------------------------------------------------------
__global__ __launch_bounds__(256) void k_wkv(const float* __restrict__ faaaa)
{
    __shared__ float sh[8][4][64];
    const int tid = threadIdx.x;
    const int bh = blockIdx.x;
    const int b = bh >> 5, h = bh & 31;
    const int m = tid >> 2, s = tid & 3;
    const int n0 = s << 4;
    const int colbase = h << 6;

    const int which = tid >> 6;
    const int idx = tid & 63;
    const float* srcs[4] = {g_r, g_k, g_v, g_w};
    const float* myp = srcs[which] + (size_t)b * TSEQ * CDIM + colbase + idx;
    const uint32_t mydst = su32(&sh[0][which][idx]);

    unsigned long long u2[8];
    {
        const unsigned long long* up = (const unsigned long long*)(faaaa + colbase + n0);
#pragma unroll
        for (int i = 0; i < 8; i++) u2[i] = up[i];
    }
    unsigned long long st[8];
#pragma unroll
    for (int i = 0; i < 8; i++) st[i] = 0ull;

#pragma unroll
    for (int d = 0; d < 6; d++) {
        cp4(mydst + (uint32_t)d * 1024, myp + (size_t)d * CDIM);
        CP_COMMIT();
    }

    float* outp = g_a + (size_t)b * TSEQ * CDIM + colbase + m;

    for (int t = 0; t < TSEQ; t++) {
        if (t + 6 < TSEQ)
            cp4(mydst + (uint32_t)((t + 6) & 7) * 1024, myp + (size_t)(t + 6) * CDIM);
        CP_COMMIT();
        CP_WAIT6();
        __syncthreads();

        const int slot = t & 7;
        float vm = sh[slot][2][m];
        unsigned long long v2 = f2_pack(vm, vm);
        const unsigned long long* rp = (const unsigned long long*)&sh[slot][0][n0];
        const unsigned long long* kp = (const unsigned long long*)&sh[slot][1][n0];
        const unsigned long long* wp = (const unsigned long long*)&sh[slot][3][n0];

        unsigned long long acc2 = 0ull;
#pragma unroll
        for (int i = 0; i < 8; i++) {
            unsigned long long kv  = f2_mul(kp[i], v2);
            unsigned long long tmp = f2_fma(u2[i], kv, st[i]);
            acc2 = f2_fma(rp[i], tmp, acc2);
            st[i] = f2_fma(wp[i], st[i], kv);
        }
        float lo, hi;
        f2_unpack(acc2, lo, hi);
        float acc = lo + hi;
        acc += __shfl_xor_sync(0xffffffffu, acc, 1);
        acc += __shfl_xor_sync(0xffffffffu, acc, 2);
        if (s == 0) outp[(size_t)t * CDIM] = acc;
    }
}

// ---------------------------------------------------------------------------
// GroupNorm * ln_w + ln_b, * gate -> fragment-packed tf32 g_ypack
// ---------------------------------------------------------------------------
__global__ __launch_bounds__(1024) void k_gnmul(const float* __restrict__ lnw,
                                                const float* __restrict__ lnb)
{
    const int row = blockIdx.x;
    const int wp = threadIdx.x >> 5;
    const int l = threadIdx.x & 31;
    const int c0 = wp * 64 + l;
    const size_t base = (size_t)row * CDIM;

    float a0 = g_a[base + c0];
    float a1 = g_a[base + c0 + 32];
    float s = a0 + a1;
    float q = a0 * a0 + a1 * a1;
#pragma unroll
    for (int off = 16; off; off >>= 1) {
        s += __shfl_xor_sync(0xffffffffu, s, off);
        q += __shfl_xor_sync(0xffffffffu, q, off);
    }
    float mean = s * (1.f / 64.f);
    float var = q * (1.f / 64.f) - mean * mean;
    float rstd = rsqrtf(var + GN_EPS);
    float y0 = (a0 - mean) * rstd * lnw[c0] + lnb[c0];
    float y1 = (a1 - mean) * rstd * lnw[c0 + 32] + lnb[c0 + 32];
    g_ypack[packA_idx(row, c0)]      = tf32r(y0 * g_gt[base + c0]);
    g_ypack[packA_idx(row, c0 + 32)] = tf32r(y1 * g_gt[base + c0 + 32]);
}

// ---------------------------------------------------------------------------
// Launch: fork/join graph
//   s2: packB (join before rkv GEMM)
//   main: t5 -> lerp5 -> gemm_rkv -> [join decay] -> wkv -> [join gate]
//         -> gnmul -> gemm1
//   s1: decay_h -> decay_w (fork after lerp5) -> [wait eRKV] -> gemm_g
// ---------------------------------------------------------------------------
extern "C" void kernel_launch(void* const* d_in, const int* in_sizes, int n_in,
                              void* d_out, int out_size)
{
    const float* x     = (const float*)d_in[0];
    const float* maa_x = (const float*)d_in[1];
    const float* maa_w = (const float*)d_in[2];
    const float* maa_k = (const float*)d_in[3];
    const float* maa_v = (const float*)d_in[4];
    const float* maa_r = (const float*)d_in[5];
    const float* maa_g = (const float*)d_in[6];
    const float* w1    = (const float*)d_in[7];
    const float* w2    = (const float*)d_in[8];
    const float* tdec  = (const float*)d_in[9];
    const float* dw1   = (const float*)d_in[10];
    const float* dw2   = (const float*)d_in[11];
    const float* u     = (const float*)d_in[12];
    const float* w_r   = (const float*)d_in[13];
    const float* w_k   = (const float*)d_in[14];
    const float* w_v   = (const float*)d_in[15];
    const float* w_g   = (const float*)d_in[16];
    const float* w_o   = (const float*)d_in[17];
    const float* lnw   = (const float*)d_in[18];
    const float* lnb   = (const float*)d_in[19];
    float* out = (float*)d_out;

    float *p_apack, *p_ypack, *p_wpack, *p_r, *p_k, *p_v, *p_g;
    cudaGetSymbolAddress((void**)&p_apack, g_apack);
    cudaGetSymbolAddress((void**)&p_ypack, g_ypack);
    cudaGetSymbolAddress((void**)&p_wpack, g_wpack);
    cudaGetSymbolAddress((void**)&p_r, g_r);
    cudaGetSymbolAddress((void**)&p_k, g_k);
    cudaGetSymbolAddress((void**)&p_v, g_v);
    cudaGetSymbolAddress((void**)&p_g, g_gt);

    const size_t MC = (size_t)MTOT * CDIM;
    const size_t WSLOT = (size_t)CDIM * CDIM;
    const int GEMM_SMEM = 3 * 32768;   // 98304 -> 2 CTAs/SM

    cudaFuncSetAttribute(k_gemm_rkv, cudaFuncAttributeMaxDynamicSharedMemorySize, GEMM_SMEM);
    cudaFuncSetAttribute(k_gemm_g, cudaFuncAttributeMaxDynamicSharedMemorySize, GEMM_SMEM);
    cudaFuncSetAttribute(k_gemm1, cudaFuncAttributeMaxDynamicSharedMemorySize, GEMM_SMEM);

    // fork s2: weight packing
    cudaEventRecord(g_env.evRoot, 0);
    cudaStreamWaitEvent(g_env.s2, g_env.evRoot, 0);
    dim3 pg(16384, 5);
    k_packB_all<<<pg, 256, 0, g_env.s2>>>(w_r, w_k, w_v, w_g, w_o, p_wpack);
    cudaEventRecord(g_env.ePack, g_env.s2);

    // main: t5 -> lerp5
    k_prep_t5<<<MTOT / 64, 256>>>(x, maa_x, w1);
    k_lerp5<<<(MTOT / 16) * 8, 256>>>(x, w2, maa_w, maa_k, maa_v, maa_r, maa_g);

    // fork s1: decay chain
    cudaEventRecord(g_env.eLerp, 0);
    cudaStreamWaitEvent(g_env.s1, g_env.eLerp, 0);
    k_decay_h<<<MTOT / 64, 256, 0, g_env.s1>>>(dw1);
    k_decay_w<<<(MTOT / 16) * 8, 256, 0, g_env.s1>>>(dw2, tdec);
    cudaEventRecord(g_env.eDecay, g_env.s1);

    // main: join packB, r/k/v projections only
    cudaStreamWaitEvent(0, g_env.ePack, 0);
    dim3 gg3(CDIM / 128, MTOT / 128, 3);
    k_gemm_rkv<<<gg3, 128, GEMM_SMEM>>>(p_apack, p_wpack, p_r, p_k, p_v);
    cudaEventRecord(g_env.eRKV, 0);

    // s1: gate projection concurrent with wkv
    cudaStreamWaitEvent(g_env.s1, g_env.eRKV, 0);
    dim3 gg(CDIM / 128, MTOT / 128);
    k_gemm_g<<<gg, 128, GEMM_SMEM, g_env.s1>>>(p_apack + 3 * MC, p_wpack + 3 * WSLOT, p_g);
    cudaEventRecord(g_env.eGate, g_env.s1);

    // main: join decay, run scan; join gate; gn; output proj
    cudaStreamWaitEvent(0, g_env.eDecay, 0);
    k_wkv<<<BB * HHEADS, 256>>>(u);

    cudaStreamWaitEvent(0, g_env.eGate, 0);
    k_gnmul<<<MTOT, 1024>>>(lnw, lnb);

    k_gemm1<<<gg, 128, GEMM_SMEM>>>(p_ypack, p_wpack + 4 * WSLOT, out);
}

// round 15
// speedup vs baseline: 1.2575x; 1.2575x over previous
#include <cuda_runtime.h>
#include <cuda_bf16.h>
#include <cstddef>
#include <cstdint>

// Problem constants
#define BB    4
#define TSEQ  2048
#define CDIM  2048
#define MTOT  8192          // BB*TSEQ
#define HHEADS 32
#define NSZ   64
#define GN_EPS 6.4e-4f      // 1e-5 * 8^2

// ---------------------------------------------------------------------------
// Scratch
// ---------------------------------------------------------------------------
__device__ float g_apack[4ull * MTOT * CDIM];   // fragment-packed tf32: xk,xv,xr,xg
__device__ float g_ypack[(size_t)MTOT * CDIM];  // fragment-packed gn*gate
__device__ float g_wpack[5ull * CDIM * CDIM];   // fragment-packed weights: r,k,v,g,o
__device__ float g_xd  [(size_t)MTOT * CDIM];
__device__ float g_t5  [MTOT * 160];
__device__ float g_r   [(size_t)MTOT * CDIM];
__device__ float g_k   [(size_t)MTOT * CDIM];
__device__ float g_v   [(size_t)MTOT * CDIM];
__device__ float g_gt  [(size_t)MTOT * CDIM];
__device__ float g_w   [(size_t)MTOT * CDIM];
__device__ float g_h   [MTOT * 64];
__device__ float g_a   [(size_t)MTOT * CDIM];

// ---------------------------------------------------------------------------
// side streams + events for graph-captured fork/join
// ---------------------------------------------------------------------------
struct StreamEnv {
    cudaStream_t s1 = nullptr, s2 = nullptr;
    cudaEvent_t evRoot = nullptr, ePack = nullptr, eLerp = nullptr, eDecay = nullptr;
    StreamEnv() {
        cudaStreamCreateWithFlags(&s1, cudaStreamNonBlocking);
        cudaStreamCreateWithFlags(&s2, cudaStreamNonBlocking);
        cudaEventCreateWithFlags(&evRoot, cudaEventDisableTiming);
        cudaEventCreateWithFlags(&ePack, cudaEventDisableTiming);
        cudaEventCreateWithFlags(&eLerp, cudaEventDisableTiming);
        cudaEventCreateWithFlags(&eDecay, cudaEventDisableTiming);
    }
};
static StreamEnv g_env;

// ---------------------------------------------------------------------------
// helpers
// ---------------------------------------------------------------------------
__device__ __forceinline__ unsigned long long f2_pack(float lo, float hi) {
    unsigned long long r;
    asm("mov.b64 %0, {%1, %2};" : "=l"(r) : "f"(lo), "f"(hi));
    return r;
}
__device__ __forceinline__ void f2_unpack(unsigned long long v, float& lo, float& hi) {
    asm("mov.b64 {%0, %1}, %2;" : "=f"(lo), "=f"(hi) : "l"(v));
}
__device__ __forceinline__ unsigned long long f2_fma(unsigned long long a,
                                                     unsigned long long b,
                                                     unsigned long long c) {
    unsigned long long d;
    asm("fma.rn.f32x2 %0, %1, %2, %3;" : "=l"(d) : "l"(a), "l"(b), "l"(c));
    return d;
}
__device__ __forceinline__ unsigned long long f2_mul(unsigned long long a,
                                                     unsigned long long b) {
    unsigned long long d;
    asm("mul.rn.f32x2 %0, %1, %2;" : "=l"(d) : "l"(a), "l"(b));
    return d;
}
__device__ __forceinline__ float tf32r(float x) {
    uint32_t u;
    asm("cvt.rna.tf32.f32 %0, %1;" : "=r"(u) : "f"(x));
    return __uint_as_float(u);
}
__device__ __forceinline__ uint32_t su32(const void* p) {
    uint32_t a;
    asm("{ .reg .u64 t; cvta.to.shared.u64 t, %1; cvt.u32.u64 %0, t; }" : "=r"(a) : "l"(p));
    return a;
}
__device__ __forceinline__ void cp16(uint32_t dst, const void* src) {
    asm volatile("cp.async.cg.shared.global [%0], [%1], 16;" :: "r"(dst), "l"(src));
}
__device__ __forceinline__ void cp4(uint32_t dst, const void* src) {
    asm volatile("cp.async.ca.shared.global [%0], [%1], 4;" :: "r"(dst), "l"(src));
}
#define CP_COMMIT() asm volatile("cp.async.commit_group;" ::: "memory")
#define CP_WAIT1()  asm volatile("cp.async.wait_group 1;" ::: "memory")
#define CP_WAIT6()  asm volatile("cp.async.wait_group 6;" ::: "memory")

__device__ __forceinline__ void mma8(float* c, const uint32_t* a, const uint32_t* b) {
    asm volatile(
        "mma.sync.aligned.m16n8k8.row.col.f32.tf32.tf32.f32 "
        "{%0,%1,%2,%3}, {%4,%5,%6,%7}, {%8,%9}, {%0,%1,%2,%3};"
        : "+f"(c[0]), "+f"(c[1]), "+f"(c[2]), "+f"(c[3])
        : "r"(a[0]), "r"(a[1]), "r"(a[2]), "r"(a[3]), "r"(b[0]), "r"(b[1]));
}

// -------- fragment-packed global layouts --------
__device__ __forceinline__ size_t packA_idx(int m, int k) {
    int r = m & 15, c = k & 7;
    int lane = ((r & 7) << 2) | (c & 3);
    int i = (r >> 3) | ((c >> 2) << 1);
    int atom = (((m >> 4) & 7) << 2) | ((k >> 3) & 3);
    size_t tile = ((size_t)(m >> 7) << 6) + (size_t)(k >> 5);
    return (tile << 12) + (size_t)((atom << 7) + (lane << 2) + i);
}
__device__ __forceinline__ size_t packB_idx(int n, int k) {
    int lane = ((n & 7) << 2) | (k & 3);
    int j = (k >> 2) & 1;
    int atom = (((n >> 3) & 31) << 2) | ((k >> 3) & 3);
    size_t tile = ((size_t)(n >> 8) << 6) + (size_t)(k >> 5);
    return (tile << 13) + (size_t)((atom << 6) + (lane << 1) + j);
}

// ---------------------------------------------------------------------------
// pack all 5 weights
// ---------------------------------------------------------------------------
__global__ __launch_bounds__(256) void k_packB_all(const float* __restrict__ w0,
                                                   const float* __restrict__ w1,
                                                   const float* __restrict__ w2,
                                                   const float* __restrict__ w3,
                                                   const float* __restrict__ w4,
                                                   float* __restrict__ o)
{
    const float* ws[5] = {w0, w1, w2, w3, w4};
    const float* w = ws[blockIdx.y];
    float* oo = o + (size_t)blockIdx.y * CDIM * CDIM;
    int g = blockIdx.x * 256 + threadIdx.x;
    int n = g >> 11, k = g & 2047;
    oo[packB_idx(n, k)] = tf32r(w[g]);
}

// ---------------------------------------------------------------------------
// t5 = tanh( (x + (shift(x)-x)*maa_x) @ W1 )   [M,160]
// ---------------------------------------------------------------------------
__global__ __launch_bounds__(256) void k_prep_t5(const float* __restrict__ x,
                                                 const float* __restrict__ maa_x,
                                                 const float* __restrict__ w1)
{
    __shared__ float As[64][33];
    __shared__ float Bs[32][160];
    const int tid = threadIdx.x;
    const int row0 = blockIdx.x * 64;
    const int tx = tid & 31, ty = tid >> 5;
    const int col0 = tx * 5, r0 = ty * 8;

    float acc[8][5];
#pragma unroll
    for (int i = 0; i < 8; i++)
#pragma unroll
        for (int j = 0; j < 5; j++) acc[i][j] = 0.f;

    for (int k0 = 0; k0 < CDIM; k0 += 32) {
        __syncthreads();
#pragma unroll
        for (int i = 0; i < 8; i++) {
            int lin = i * 256 + tid;
            int r = lin >> 5, kk = lin & 31;
            int gr = row0 + r, gc = k0 + kk;
            float xv = x[(size_t)gr * CDIM + gc];
            float xp = (gr & (TSEQ - 1)) ? x[(size_t)(gr - 1) * CDIM + gc] : 0.f;
            As[r][kk] = xv + (xp - xv) * maa_x[gc];
        }
#pragma unroll
        for (int i = 0; i < 20; i++) {
            int lin = i * 256 + tid;
            int kk = lin / 160, c = lin - kk * 160;
            Bs[kk][c] = w1[(size_t)(k0 + kk) * 160 + c];
        }
        __syncthreads();
#pragma unroll
        for (int kk = 0; kk < 32; kk++) {
            float a[8], b[5];
#pragma unroll
            for (int i = 0; i < 8; i++) a[i] = As[r0 + i][kk];
#pragma unroll
            for (int j = 0; j < 5; j++) b[j] = Bs[kk][col0 + j];
#pragma unroll
            for (int i = 0; i < 8; i++)
#pragma unroll
                for (int j = 0; j < 5; j++)
                    acc[i][j] = fmaf(a[i], b[j], acc[i][j]);
        }
    }
#pragma unroll
    for (int i = 0; i < 8; i++)
#pragma unroll
        for (int j = 0; j < 5; j++)
            g_t5[(size_t)(row0 + r0 + i) * 160 + col0 + j] = tanhf(acc[i][j]);
}

// ---------------------------------------------------------------------------
// for f in 0..4: lerp_f = x + xx*(maa_f + t5[:,f,:] @ w2[f])   (R5 version)
// ---------------------------------------------------------------------------
__global__ __launch_bounds__(256) void k_lerp5(const float* __restrict__ x,
                                               const float* __restrict__ w2,
                                               const float* __restrict__ maa_w,
                                               const float* __restrict__ maa_k,
                                               const float* __restrict__ maa_v,
                                               const float* __restrict__ maa_r,
                                               const float* __restrict__ maa_g)
{
    __shared__ float t5s[16][160];
    __shared__ float w2s[32][256];
    const int tid = threadIdx.x;
    const int ct = blockIdx.x & 7;
    const int rt = blockIdx.x >> 3;
    const int row0 = rt * 16;
    const int c = ct * 256 + tid;
    const size_t MC = (size_t)MTOT * CDIM;

#pragma unroll
    for (int i = 0; i < 10; i++) {
        int lin = i * 256 + tid;
        int r = lin / 160, e = lin - r * 160;
        t5s[r][e] = g_t5[(size_t)(row0 + r) * 160 + e];
    }
    float xv[16], xxv[16];
#pragma unroll
    for (int r = 0; r < 16; r++) {
        int gr = row0 + r;
        float v = x[(size_t)gr * CDIM + c];
        float p = (gr & (TSEQ - 1)) ? x[(size_t)(gr - 1) * CDIM + c] : 0.f;
        xv[r] = v; xxv[r] = p - v;
    }
    const float* maas[5] = {maa_w, maa_k, maa_v, maa_r, maa_g};

    for (int f = 0; f < 5; f++) {
        __syncthreads();
#pragma unroll
        for (int e = 0; e < 32; e++)
            w2s[e][tid] = w2[(size_t)(f * 32 + e) * CDIM + c];
        __syncthreads();

        float acc[16];
#pragma unroll
        for (int r = 0; r < 16; r++) acc[r] = 0.f;
#pragma unroll
        for (int e = 0; e < 32; e++) {
            float we = w2s[e][tid];
#pragma unroll
            for (int r = 0; r < 16; r++)
                acc[r] = fmaf(t5s[r][f * 32 + e], we, acc[r]);
        }
        float mb = maas[f][c];
        if (f == 0) {
#pragma unroll
            for (int r = 0; r < 16; r++)
                g_xd[(size_t)(row0 + r) * CDIM + c] = xv[r] + xxv[r] * (mb + acc[r]);
        } else {
            float* outp = g_apack + (size_t)(f - 1) * MC;
#pragma unroll
            for (int r = 0; r < 16; r++)
                outp[packA_idx(row0 + r, c)] = tf32r(xv[r] + xxv[r] * (mb + acc[r]));
        }
    }
}

// ---------------------------------------------------------------------------
// tf32 mma.sync GEMM body (R11 known-best)
// ---------------------------------------------------------------------------
__device__ __forceinline__ void gemm_body(const float* __restrict__ Ap,
                                          const float* __restrict__ Bp,
                                          float* __restrict__ Co,
                                          int bx, int by, bool silu,
                                          float* sm)
{
    const int tid = threadIdx.x;
    const int lane = tid & 31, wid = tid >> 5;
    const int warp_m = wid >> 1, warp_n = wid & 1;

    const float* Ag = Ap + ((size_t)by << 6 << 12);
    const float* Bg = Bp + ((size_t)(bx >> 1) << 6 << 13)
                         + (size_t)(bx & 1) * 4096;
    const uint32_t sbase = su32(sm);

    float c[4][8][4];
#pragma unroll
    for (int fm = 0; fm < 4; fm++)
#pragma unroll
        for (int fn = 0; fn < 8; fn++)
#pragma unroll
            for (int i = 0; i < 4; i++) c[fm][fn][i] = 0.f;

#define ISSUE(kt)                                                                  \
    do {                                                                           \
        uint32_t d = sbase + ((kt) % 3) * 32768;                                   \
        const float4* a4 = (const float4*)(Ag + ((size_t)(kt) << 12));             \
        const float4* b4 = (const float4*)(Bg + ((size_t)(kt) << 13));             \
        _Pragma("unroll")                                                          \
        for (int i = 0; i < 8; i++)                                                \
            cp16(d + (uint32_t)(tid + i * 128) * 16, a4 + tid + i * 128);          \
        _Pragma("unroll")                                                          \
        for (int i = 0; i < 8; i++)                                                \
            cp16(d + 16384 + (uint32_t)(tid + i * 128) * 16, b4 + tid + i * 128);  \
    } while (0)

#define LOAD_FRAG(ks, abuf, bbuf)                                                   \
    do {                                                                            \
        _Pragma("unroll")                                                           \
        for (int fm = 0; fm < 4; fm++) {                                            \
            const uint4* p = (const uint4*)As + (((warp_m * 4 + fm) * 4 + (ks)) * 32 + lane); \
            uint4 v = *p;                                                           \
            (abuf)[fm][0] = v.x; (abuf)[fm][1] = v.y;                               \
            (abuf)[fm][2] = v.z; (abuf)[fm][3] = v.w;                               \
        }                                                                           \
        _Pragma("unroll")                                                           \
        for (int fn = 0; fn < 8; fn++) {                                            \
            const uint2* p = (const uint2*)Bs + (((warp_n * 8 + fn) * 4 + (ks)) * 32 + lane); \
            uint2 v = *p;                                                           \
            (bbuf)[fn][0] = v.x; (bbuf)[fn][1] = v.y;                               \
        }                                                                           \
    } while (0)

    ISSUE(0); CP_COMMIT();
    ISSUE(1); CP_COMMIT();

    uint32_t a[2][4][4], b[2][8][2];

    for (int kt = 0; kt < 64; kt++) {
        CP_WAIT1();
        __syncthreads();
        if (kt + 2 < 64) ISSUE(kt + 2);
        CP_COMMIT();

        const float* As = sm + (kt % 3) * 8192;
        const float* Bs = As + 4096;

        LOAD_FRAG(0, a[0], b[0]);
#pragma unroll
        for (int ks = 0; ks < 4; ks++) {
            const int cur = ks & 1;
            if (ks < 3) LOAD_FRAG(ks + 1, a[cur ^ 1], b[cur ^ 1]);
#pragma unroll
            for (int fm = 0; fm < 4; fm++)
#pragma unroll
                for (int fn = 0; fn < 8; fn++)
                    mma8(c[fm][fn], a[cur][fm], b[cur][fn]);
        }
    }
#undef ISSUE
#undef LOAD_FRAG

    const int r0 = by * 128 + warp_m * 64 + (lane >> 2);
    const int c0 = bx * 128 + warp_n * 64 + (lane & 3) * 2;
#pragma unroll
    for (int fm = 0; fm < 4; fm++) {
#pragma unroll
        for (int fn = 0; fn < 8; fn++) {
            int row = r0 + fm * 16;
            int col = c0 + fn * 8;
            float2 v0 = make_float2(c[fm][fn][0], c[fm][fn][1]);
            float2 v1 = make_float2(c[fm][fn][2], c[fm][fn][3]);
            if (silu) {
                v0.x = v0.x / (1.f + expf(-v0.x));
                v0.y = v0.y / (1.f + expf(-v0.y));
                v1.x = v1.x / (1.f + expf(-v1.x));
                v1.y = v1.y / (1.f + expf(-v1.y));
            }
            *(float2*)(Co + (size_t)row * CDIM + col) = v0;
            *(float2*)(Co + (size_t)(row + 8) * CDIM + col) = v1;
        }
    }
}

// fused 4-projection GEMM: blockIdx.z picks operands (r,k,v,g)
__global__ __launch_bounds__(128) void k_gemm4(const float* __restrict__ Abase,
                                               const float* __restrict__ Wbase,
                                               float* __restrict__ o_r,
                                               float* __restrict__ o_k,
                                               float* __restrict__ o_v,
                                               float* __restrict__ o_g)
{
    extern __shared__ __align__(16) float sm[];
    const int z = blockIdx.z;
    const size_t MC = (size_t)MTOT * CDIM;
    const size_t WSLOT = (size_t)CDIM * CDIM;
    const int aslot = (z == 0) ? 2 : (z == 1) ? 0 : (z == 2) ? 1 : 3;
    float* Co = (z == 0) ? o_r : (z == 1) ? o_k : (z == 2) ? o_v : o_g;
    gemm_body(Abase + (size_t)aslot * MC, Wbase + (size_t)z * WSLOT, Co,
              blockIdx.x, blockIdx.y, z == 3, sm);
}

// single GEMM (output projection)
__global__ __launch_bounds__(128) void k_gemm1(const float* __restrict__ Ap,
                                               const float* __restrict__ Bp,
                                               float* __restrict__ Co)
{
    extern __shared__ __align__(16) float sm[];
    gemm_body(Ap, Bp, Co, blockIdx.x, blockIdx.y, false, sm);
}

// ---------------------------------------------------------------------------
// h = tanh(xd @ dw1)  [M,64]
// ---------------------------------------------------------------------------
__global__ __launch_bounds__(256) void k_decay_h(const float* __restrict__ dw1)
{
    __shared__ float As[64][33];
    __shared__ float Bs[32][64];
    const int tid = threadIdx.x;
    const int row0 = blockIdx.x * 64;
    const int tx = tid & 15, ty = tid >> 4;
    const int col0 = tx * 4, r0 = ty * 4;

    float acc[4][4];
#pragma unroll
    for (int i = 0; i < 4; i++)
#pragma unroll
        for (int j = 0; j < 4; j++) acc[i][j] = 0.f;

    for (int k0 = 0; k0 < CDIM; k0 += 32) {
        __syncthreads();
#pragma unroll
        for (int i = 0; i < 8; i++) {
            int lin = i * 256 + tid;
            int r = lin >> 5, kk = lin & 31;
            As[r][kk] = g_xd[(size_t)(row0 + r) * CDIM + k0 + kk];
        }
#pragma unroll
        for (int i = 0; i < 8; i++) {
            int lin = i * 256 + tid;
            int kk = lin >> 6, cc = lin & 63;
            Bs[kk][cc] = dw1[(size_t)(k0 + kk) * 64 + cc];
        }
        __syncthreads();
#pragma unroll
        for (int kk = 0; kk < 32; kk++) {
            float a[4], b[4];
#pragma unroll
            for (int i = 0; i < 4; i++) a[i] = As[r0 + i][kk];
#pragma unroll
            for (int j = 0; j < 4; j++) b[j] = Bs[kk][col0 + j];
#pragma unroll
            for (int i = 0; i < 4; i++)
#pragma unroll
                for (int j = 0; j < 4; j++)
                    acc[i][j] = fmaf(a[i], b[j], acc[i][j]);
        }
    }
#pragma unroll
    for (int i = 0; i < 4; i++)
#pragma unroll
        for (int j = 0; j < 4; j++)
            g_h[(size_t)(row0 + r0 + i) * 64 + col0 + j] = tanhf(acc[i][j]);
}

// ---------------------------------------------------------------------------
// w = exp(-exp(time_decay + h @ dw2))  [M,C]
// ---------------------------------------------------------------------------
__global__ __launch_bounds__(256) void k_decay_w(const float* __restrict__ dw2,
                                                 const float* __restrict__ tdec)
{
    __shared__ float hs[16][64];
    __shared__ float ws[32][256];
    const int tid = threadIdx.x;
    const int ct = blockIdx.x & 7;
    const int rt = blockIdx.x >> 3;
    const int row0 = rt * 16;
    const int c = ct * 256 + tid;

#pragma unroll
    for (int i = 0; i < 4; i++) {
        int lin = i * 256 + tid;
        int r = lin >> 6, e = lin & 63;
        hs[r][e] = g_h[(size_t)(row0 + r) * 64 + e];
    }
    float acc[16];
#pragma unroll
    for (int r = 0; r < 16; r++) acc[r] = 0.f;

    for (int ch = 0; ch < 2; ch++) {
        __syncthreads();
#pragma unroll
        for (int e = 0; e < 32; e++)
            ws[e][tid] = dw2[(size_t)(ch * 32 + e) * CDIM + c];
        __syncthreads();
#pragma unroll
        for (int e = 0; e < 32; e++) {
            float we = ws[e][tid];
#pragma unroll
            for (int r = 0; r < 16; r++)
                acc[r] = fmaf(hs[r][ch * 32 + e], we, acc[r]);
        }
    }
    float tb = tdec[c];
#pragma unroll
    for (int r = 0; r < 16; r++)
        g_w[(size_t)(row0 + r) * CDIM + c] = expf(-expf(tb + acc[r]));
}

// ---------------------------------------------------------------------------
// WKV scan. One block per (b,h). 256 thr = 64 value cols x 4 key splits.
// 16-deep cp.async ring, prefetch distance 6, TWO timesteps per barrier
// (halves commit/wait/barrier overhead on the serial critical path).
// ---------------------------------------------------------------------------
__global__ __launch_bounds__(256) void k_wkv(const float* __restrict__ faaaa)
{
    __shared__ float sh[16][4][64];   // 16-slot ring (needed for 2-step safety)
    const int tid = threadIdx.x;
    const int bh = blockIdx.x;
    const int b = bh >> 5, h = bh & 31;
    const int m = tid >> 2, s = tid & 3;
    const int n0 = s << 4;
    const int colbase = h << 6;

    const int which = tid >> 6;
    const int idx = tid & 63;
    const float* srcs[4] = {g_r, g_k, g_v, g_w};
    const float* myp = srcs[which] + (size_t)b * TSEQ * CDIM + colbase + idx;
    const uint32_t mydst = su32(&sh[0][which][idx]);   // slot stride 1024B

    unsigned long long u2[8];
    {
        const unsigned long long* up = (const unsigned long long*)(faaaa + colbase + n0);
#pragma unroll
        for (int i = 0; i < 8; i++) u2[i] = up[i];
    }
    unsigned long long st[8];
#pragma unroll
    for (int i = 0; i < 8; i++) st[i] = 0ull;

    // prologue: prefetch steps 0..5 (one commit group each)
#pragma unroll
    for (int d = 0; d < 6; d++) {
        cp4(mydst + (uint32_t)d * 1024, myp + (size_t)d * CDIM);
        CP_COMMIT();
    }

    float* outp = g_a + (size_t)b * TSEQ * CDIM + colbase + m;

    for (int t = 0; t < TSEQ; t += 2) {
        if (t + 6 < TSEQ)
            cp4(mydst + (uint32_t)((t + 6) & 15) * 1024, myp + (size_t)(t + 6) * CDIM);
        CP_COMMIT();
        if (t + 7 < TSEQ)
            cp4(mydst + (uint32_t)((t + 7) & 15) * 1024, myp + (size_t)(t + 7) * CDIM);
        CP_COMMIT();
        CP_WAIT6();            // slots t, t+1 complete
        __syncthreads();

#pragma unroll
        for (int step = 0; step < 2; step++) {
            const int slot = (t + step) & 15;
            float vm = sh[slot][2][m];
            unsigned long long v2 = f2_pack(vm, vm);
            const unsigned long long* rp = (const unsigned long long*)&sh[slot][0][n0];
            const unsigned long long* kp = (const unsigned long long*)&sh[slot][1][n0];
            const unsigned long long* wp = (const unsigned long long*)&sh[slot][3][n0];

            unsigned long long acc2 = 0ull;
#pragma unroll
            for (int i = 0; i < 8; i++) {
                unsigned long long kv  = f2_mul(kp[i], v2);
                unsigned long long tmp = f2_fma(u2[i], kv, st[i]);
                acc2 = f2_fma(rp[i], tmp, acc2);
                st[i] = f2_fma(wp[i], st[i], kv);
            }
            float lo, hi;
            f2_unpack(acc2, lo, hi);
            float acc = lo + hi;
            acc += __shfl_xor_sync(0xffffffffu, acc, 1);
            acc += __shfl_xor_sync(0xffffffffu, acc, 2);
            if (s == 0) outp[(size_t)(t + step) * CDIM] = acc;
        }
    }
}

// ---------------------------------------------------------------------------
// GroupNorm * ln_w + ln_b, * gate -> fragment-packed tf32 g_ypack
// ---------------------------------------------------------------------------
__global__ __launch_bounds__(1024) void k_gnmul(const float* __restrict__ lnw,
                                                const float* __restrict__ lnb)
{
    const int row = blockIdx.x;
    const int wp = threadIdx.x >> 5;
    const int l = threadIdx.x & 31;
    const int c0 = wp * 64 + l;
    const size_t base = (size_t)row * CDIM;

    float a0 = g_a[base + c0];
    float a1 = g_a[base + c0 + 32];
    float s = a0 + a1;
    float q = a0 * a0 + a1 * a1;
#pragma unroll
    for (int off = 16; off; off >>= 1) {
        s += __shfl_xor_sync(0xffffffffu, s, off);
        q += __shfl_xor_sync(0xffffffffu, q, off);
    }
    float mean = s * (1.f / 64.f);
    float var = q * (1.f / 64.f) - mean * mean;
    float rstd = rsqrtf(var + GN_EPS);
    float y0 = (a0 - mean) * rstd * lnw[c0] + lnb[c0];
    float y1 = (a1 - mean) * rstd * lnw[c0 + 32] + lnb[c0 + 32];
    g_ypack[packA_idx(row, c0)]      = tf32r(y0 * g_gt[base + c0]);
    g_ypack[packA_idx(row, c0 + 32)] = tf32r(y1 * g_gt[base + c0 + 32]);
}

// ---------------------------------------------------------------------------
// Launch: R13 fork/join graph (wkv runs ALONE — never co-schedule with it)
//   s2: packB  (joined before gemm4)
//   main: prep_t5 -> lerp5 -> gemm4 -> [join decay] -> wkv -> gnmul -> gemm1
//   s1: decay_h -> decay_w (forked after lerp5, joined before wkv)
// ---------------------------------------------------------------------------
extern "C" void kernel_launch(void* const* d_in, const int* in_sizes, int n_in,
                              void* d_out, int out_size)
{
    const float* x     = (const float*)d_in[0];
    const float* maa_x = (const float*)d_in[1];
    const float* maa_w = (const float*)d_in[2];
    const float* maa_k = (const float*)d_in[3];
    const float* maa_v = (const float*)d_in[4];
    const float* maa_r = (const float*)d_in[5];
    const float* maa_g = (const float*)d_in[6];
    const float* w1    = (const float*)d_in[7];
    const float* w2    = (const float*)d_in[8];
    const float* tdec  = (const float*)d_in[9];
    const float* dw1   = (const float*)d_in[10];
    const float* dw2   = (const float*)d_in[11];
    const float* u     = (const float*)d_in[12];
    const float* w_r   = (const float*)d_in[13];
    const float* w_k   = (const float*)d_in[14];
    const float* w_v   = (const float*)d_in[15];
    const float* w_g   = (const float*)d_in[16];
    const float* w_o   = (const float*)d_in[17];
    const float* lnw   = (const float*)d_in[18];
    const float* lnb   = (const float*)d_in[19];
    float* out = (float*)d_out;

    float *p_apack, *p_ypack, *p_wpack, *p_r, *p_k, *p_v, *p_g;
    cudaGetSymbolAddress((void**)&p_apack, g_apack);
    cudaGetSymbolAddress((void**)&p_ypack, g_ypack);
    cudaGetSymbolAddress((void**)&p_wpack, g_wpack);
    cudaGetSymbolAddress((void**)&p_r, g_r);
    cudaGetSymbolAddress((void**)&p_k, g_k);
    cudaGetSymbolAddress((void**)&p_v, g_v);
    cudaGetSymbolAddress((void**)&p_g, g_gt);

    const size_t WSLOT = (size_t)CDIM * CDIM;
    const int GEMM_SMEM = 3 * 32768;   // 98304 -> 2 CTAs/SM

    cudaFuncSetAttribute(k_gemm4, cudaFuncAttributeMaxDynamicSharedMemorySize, GEMM_SMEM);
    cudaFuncSetAttribute(k_gemm1, cudaFuncAttributeMaxDynamicSharedMemorySize, GEMM_SMEM);

    // fork s2 from main stream, run weight packing there
    cudaEventRecord(g_env.evRoot, 0);
    cudaStreamWaitEvent(g_env.s2, g_env.evRoot, 0);
    dim3 pg(16384, 5);
    k_packB_all<<<pg, 256, 0, g_env.s2>>>(w_r, w_k, w_v, w_g, w_o, p_wpack);
    cudaEventRecord(g_env.ePack, g_env.s2);

    // main: t5 -> lerp5
    k_prep_t5<<<MTOT / 64, 256>>>(x, maa_x, w1);
    k_lerp5<<<(MTOT / 16) * 8, 256>>>(x, w2, maa_w, maa_k, maa_v, maa_r, maa_g);

    // fork s1 after lerp5: decay chain (independent of gemm4)
    cudaEventRecord(g_env.eLerp, 0);
    cudaStreamWaitEvent(g_env.s1, g_env.eLerp, 0);
    k_decay_h<<<MTOT / 64, 256, 0, g_env.s1>>>(dw1);
    k_decay_w<<<(MTOT / 16) * 8, 256, 0, g_env.s1>>>(dw2, tdec);
    cudaEventRecord(g_env.eDecay, g_env.s1);

    // main: join packB, run the big fused GEMM
    cudaStreamWaitEvent(0, g_env.ePack, 0);
    dim3 gg4(CDIM / 128, MTOT / 128, 4);
    k_gemm4<<<gg4, 128, GEMM_SMEM>>>(p_apack, p_wpack, p_r, p_k, p_v, p_g);

    // main: join decay chain, then scan -> gn -> output proj
    cudaStreamWaitEvent(0, g_env.eDecay, 0);
    k_wkv<<<BB * HHEADS, 256>>>(u);

    k_gnmul<<<MTOT, 1024>>>(lnw, lnb);

    dim3 gg(CDIM / 128, MTOT / 128);
    k_gemm1<<<gg, 128, GEMM_SMEM>>>(p_ypack, p_wpack + 4 * WSLOT, out);
}

// round 16
// speedup vs baseline: 1.2892x; 1.0252x over previous
#include <cuda_runtime.h>
#include <cuda_bf16.h>
#include <cstddef>
#include <cstdint>

// Problem constants
#define BB    4
#define TSEQ  2048
#define CDIM  2048
#define MTOT  8192          // BB*TSEQ
#define HHEADS 32
#define NSZ   64
#define GN_EPS 6.4e-4f      // 1e-5 * 8^2

// ---------------------------------------------------------------------------
// Scratch
// ---------------------------------------------------------------------------
__device__ float g_apack[4ull * MTOT * CDIM];   // fragment-packed tf32: xk,xv,xr,xg
__device__ float g_ypack[(size_t)MTOT * CDIM];  // fragment-packed gn*gate
__device__ float g_wpack[5ull * CDIM * CDIM];   // fragment-packed weights: r,k,v,g,o
__device__ float g_xd  [(size_t)MTOT * CDIM];
__device__ float g_t5  [MTOT * 160];
__device__ float g_r   [(size_t)MTOT * CDIM];
__device__ float g_k   [(size_t)MTOT * CDIM];
__device__ float g_v   [(size_t)MTOT * CDIM];
__device__ float g_gt  [(size_t)MTOT * CDIM];
__device__ float g_w   [(size_t)MTOT * CDIM];
__device__ float g_h   [MTOT * 64];
__device__ float g_a   [(size_t)MTOT * CDIM];

// ---------------------------------------------------------------------------
// side streams + events for graph-captured fork/join
// ---------------------------------------------------------------------------
struct StreamEnv {
    cudaStream_t s1 = nullptr, s2 = nullptr;
    cudaEvent_t evRoot = nullptr, ePack = nullptr, eLerp = nullptr, eDecay = nullptr;
    StreamEnv() {
        cudaStreamCreateWithFlags(&s1, cudaStreamNonBlocking);
        cudaStreamCreateWithFlags(&s2, cudaStreamNonBlocking);
        cudaEventCreateWithFlags(&evRoot, cudaEventDisableTiming);
        cudaEventCreateWithFlags(&ePack, cudaEventDisableTiming);
        cudaEventCreateWithFlags(&eLerp, cudaEventDisableTiming);
        cudaEventCreateWithFlags(&eDecay, cudaEventDisableTiming);
    }
};
static StreamEnv g_env;

// ---------------------------------------------------------------------------
// helpers
// ---------------------------------------------------------------------------
__device__ __forceinline__ unsigned long long f2_pack(float lo, float hi) {
    unsigned long long r;
    asm("mov.b64 %0, {%1, %2};" : "=l"(r) : "f"(lo), "f"(hi));
    return r;
}
__device__ __forceinline__ void f2_unpack(unsigned long long v, float& lo, float& hi) {
    asm("mov.b64 {%0, %1}, %2;" : "=f"(lo), "=f"(hi) : "l"(v));
}
__device__ __forceinline__ unsigned long long f2_fma(unsigned long long a,
                                                     unsigned long long b,
                                                     unsigned long long c) {
    unsigned long long d;
    asm("fma.rn.f32x2 %0, %1, %2, %3;" : "=l"(d) : "l"(a), "l"(b), "l"(c));
    return d;
}
__device__ __forceinline__ unsigned long long f2_mul(unsigned long long a,
                                                     unsigned long long b) {
    unsigned long long d;
    asm("mul.rn.f32x2 %0, %1, %2;" : "=l"(d) : "l"(a), "l"(b));
    return d;
}
__device__ __forceinline__ float tf32r(float x) {
    uint32_t u;
    asm("cvt.rna.tf32.f32 %0, %1;" : "=r"(u) : "f"(x));
    return __uint_as_float(u);
}
__device__ __forceinline__ uint32_t su32(const void* p) {
    uint32_t a;
    asm("{ .reg .u64 t; cvta.to.shared.u64 t, %1; cvt.u32.u64 %0, t; }" : "=r"(a) : "l"(p));
    return a;
}
__device__ __forceinline__ void cp16(uint32_t dst, const void* src) {
    asm volatile("cp.async.cg.shared.global [%0], [%1], 16;" :: "r"(dst), "l"(src));
}
__device__ __forceinline__ void cp4(uint32_t dst, const void* src) {
    asm volatile("cp.async.ca.shared.global [%0], [%1], 4;" :: "r"(dst), "l"(src));
}
#define CP_COMMIT() asm volatile("cp.async.commit_group;" ::: "memory")
#define CP_WAIT1()  asm volatile("cp.async.wait_group 1;" ::: "memory")
#define CP_WAIT8()  asm volatile("cp.async.wait_group 8;" ::: "memory")

__device__ __forceinline__ void mma8(float* c, const uint32_t* a, const uint32_t* b) {
    asm volatile(
        "mma.sync.aligned.m16n8k8.row.col.f32.tf32.tf32.f32 "
        "{%0,%1,%2,%3}, {%4,%5,%6,%7}, {%8,%9}, {%0,%1,%2,%3};"
        : "+f"(c[0]), "+f"(c[1]), "+f"(c[2]), "+f"(c[3])
        : "r"(a[0]), "r"(a[1]), "r"(a[2]), "r"(a[3]), "r"(b[0]), "r"(b[1]));
}

// -------- fragment-packed global layouts --------
__device__ __forceinline__ size_t packA_idx(int m, int k) {
    int r = m & 15, c = k & 7;
    int lane = ((r & 7) << 2) | (c & 3);
    int i = (r >> 3) | ((c >> 2) << 1);
    int atom = (((m >> 4) & 7) << 2) | ((k >> 3) & 3);
    size_t tile = ((size_t)(m >> 7) << 6) + (size_t)(k >> 5);
    return (tile << 12) + (size_t)((atom << 7) + (lane << 2) + i);
}
__device__ __forceinline__ size_t packB_idx(int n, int k) {
    int lane = ((n & 7) << 2) | (k & 3);
    int j = (k >> 2) & 1;
    int atom = (((n >> 3) & 31) << 2) | ((k >> 3) & 3);
    size_t tile = ((size_t)(n >> 8) << 6) + (size_t)(k >> 5);
    return (tile << 13) + (size_t)((atom << 6) + (lane << 1) + j);
}

// ---------------------------------------------------------------------------
// pack all 5 weights
// ---------------------------------------------------------------------------
__global__ __launch_bounds__(256) void k_packB_all(const float* __restrict__ w0,
                                                   const float* __restrict__ w1,
                                                   const float* __restrict__ w2,
                                                   const float* __restrict__ w3,
                                                   const float* __restrict__ w4,
                                                   float* __restrict__ o)
{
    const float* ws[5] = {w0, w1, w2, w3, w4};
    const float* w = ws[blockIdx.y];
    float* oo = o + (size_t)blockIdx.y * CDIM * CDIM;
    int g = blockIdx.x * 256 + threadIdx.x;
    int n = g >> 11, k = g & 2047;
    oo[packB_idx(n, k)] = tf32r(w[g]);
}

// ---------------------------------------------------------------------------
// t5 = tanh( (x + (shift(x)-x)*maa_x) @ W1 )   [M,160]
// ---------------------------------------------------------------------------
__global__ __launch_bounds__(256) void k_prep_t5(const float* __restrict__ x,
                                                 const float* __restrict__ maa_x,
                                                 const float* __restrict__ w1)
{
    __shared__ float As[64][33];
    __shared__ float Bs[32][160];
    const int tid = threadIdx.x;
    const int row0 = blockIdx.x * 64;
    const int tx = tid & 31, ty = tid >> 5;
    const int col0 = tx * 5, r0 = ty * 8;

    float acc[8][5];
#pragma unroll
    for (int i = 0; i < 8; i++)
#pragma unroll
        for (int j = 0; j < 5; j++) acc[i][j] = 0.f;

    for (int k0 = 0; k0 < CDIM; k0 += 32) {
        __syncthreads();
#pragma unroll
        for (int i = 0; i < 8; i++) {
            int lin = i * 256 + tid;
            int r = lin >> 5, kk = lin & 31;
            int gr = row0 + r, gc = k0 + kk;
            float xv = x[(size_t)gr * CDIM + gc];
            float xp = (gr & (TSEQ - 1)) ? x[(size_t)(gr - 1) * CDIM + gc] : 0.f;
            As[r][kk] = xv + (xp - xv) * maa_x[gc];
        }
#pragma unroll
        for (int i = 0; i < 20; i++) {
            int lin = i * 256 + tid;
            int kk = lin / 160, c = lin - kk * 160;
            Bs[kk][c] = w1[(size_t)(k0 + kk) * 160 + c];
        }
        __syncthreads();
#pragma unroll
        for (int kk = 0; kk < 32; kk++) {
            float a[8], b[5];
#pragma unroll
            for (int i = 0; i < 8; i++) a[i] = As[r0 + i][kk];
#pragma unroll
            for (int j = 0; j < 5; j++) b[j] = Bs[kk][col0 + j];
#pragma unroll
            for (int i = 0; i < 8; i++)
#pragma unroll
                for (int j = 0; j < 5; j++)
                    acc[i][j] = fmaf(a[i], b[j], acc[i][j]);
        }
    }
#pragma unroll
    for (int i = 0; i < 8; i++)
#pragma unroll
        for (int j = 0; j < 5; j++)
            g_t5[(size_t)(row0 + r0 + i) * 160 + col0 + j] = tanhf(acc[i][j]);
}

// ---------------------------------------------------------------------------
// for f in 0..4: lerp_f = x + xx*(maa_f + t5[:,f,:] @ w2[f])   (R5 version)
// ---------------------------------------------------------------------------
__global__ __launch_bounds__(256) void k_lerp5(const float* __restrict__ x,
                                               const float* __restrict__ w2,
                                               const float* __restrict__ maa_w,
                                               const float* __restrict__ maa_k,
                                               const float* __restrict__ maa_v,
                                               const float* __restrict__ maa_r,
                                               const float* __restrict__ maa_g)
{
    __shared__ float t5s[16][160];
    __shared__ float w2s[32][256];
    const int tid = threadIdx.x;
    const int ct = blockIdx.x & 7;
    const int rt = blockIdx.x >> 3;
    const int row0 = rt * 16;
    const int c = ct * 256 + tid;
    const size_t MC = (size_t)MTOT * CDIM;

#pragma unroll
    for (int i = 0; i < 10; i++) {
        int lin = i * 256 + tid;
        int r = lin / 160, e = lin - r * 160;
        t5s[r][e] = g_t5[(size_t)(row0 + r) * 160 + e];
    }
    float xv[16], xxv[16];
#pragma unroll
    for (int r = 0; r < 16; r++) {
        int gr = row0 + r;
        float v = x[(size_t)gr * CDIM + c];
        float p = (gr & (TSEQ - 1)) ? x[(size_t)(gr - 1) * CDIM + c] : 0.f;
        xv[r] = v; xxv[r] = p - v;
    }
    const float* maas[5] = {maa_w, maa_k, maa_v, maa_r, maa_g};

    for (int f = 0; f < 5; f++) {
        __syncthreads();
#pragma unroll
        for (int e = 0; e < 32; e++)
            w2s[e][tid] = w2[(size_t)(f * 32 + e) * CDIM + c];
        __syncthreads();

        float acc[16];
#pragma unroll
        for (int r = 0; r < 16; r++) acc[r] = 0.f;
#pragma unroll
        for (int e = 0; e < 32; e++) {
            float we = w2s[e][tid];
#pragma unroll
            for (int r = 0; r < 16; r++)
                acc[r] = fmaf(t5s[r][f * 32 + e], we, acc[r]);
        }
        float mb = maas[f][c];
        if (f == 0) {
#pragma unroll
            for (int r = 0; r < 16; r++)
                g_xd[(size_t)(row0 + r) * CDIM + c] = xv[r] + xxv[r] * (mb + acc[r]);
        } else {
            float* outp = g_apack + (size_t)(f - 1) * MC;
#pragma unroll
            for (int r = 0; r < 16; r++)
                outp[packA_idx(row0 + r, c)] = tf32r(xv[r] + xxv[r] * (mb + acc[r]));
        }
    }
}

// ---------------------------------------------------------------------------
// tf32 mma.sync GEMM body (R11 known-best)
// ---------------------------------------------------------------------------
__device__ __forceinline__ void gemm_body(const float* __restrict__ Ap,
                                          const float* __restrict__ Bp,
                                          float* __restrict__ Co,
                                          int bx, int by, bool silu,
                                          float* sm)
{
    const int tid = threadIdx.x;
    const int lane = tid & 31, wid = tid >> 5;
    const int warp_m = wid >> 1, warp_n = wid & 1;

    const float* Ag = Ap + ((size_t)by << 6 << 12);
    const float* Bg = Bp + ((size_t)(bx >> 1) << 6 << 13)
                         + (size_t)(bx & 1) * 4096;
    const uint32_t sbase = su32(sm);

    float c[4][8][4];
#pragma unroll
    for (int fm = 0; fm < 4; fm++)
#pragma unroll
        for (int fn = 0; fn < 8; fn++)
#pragma unroll
            for (int i = 0; i < 4; i++) c[fm][fn][i] = 0.f;

#define ISSUE(kt)                                                                  \
    do {                                                                           \
        uint32_t d = sbase + ((kt) % 3) * 32768;                                   \
        const float4* a4 = (const float4*)(Ag + ((size_t)(kt) << 12));             \
        const float4* b4 = (const float4*)(Bg + ((size_t)(kt) << 13));             \
        _Pragma("unroll")                                                          \
        for (int i = 0; i < 8; i++)                                                \
            cp16(d + (uint32_t)(tid + i * 128) * 16, a4 + tid + i * 128);          \
        _Pragma("unroll")                                                          \
        for (int i = 0; i < 8; i++)                                                \
            cp16(d + 16384 + (uint32_t)(tid + i * 128) * 16, b4 + tid + i * 128);  \
    } while (0)

#define LOAD_FRAG(ks, abuf, bbuf)                                                   \
    do {                                                                            \
        _Pragma("unroll")                                                           \
        for (int fm = 0; fm < 4; fm++) {                                            \
            const uint4* p = (const uint4*)As + (((warp_m * 4 + fm) * 4 + (ks)) * 32 + lane); \
            uint4 v = *p;                                                           \
            (abuf)[fm][0] = v.x; (abuf)[fm][1] = v.y;                               \
            (abuf)[fm][2] = v.z; (abuf)[fm][3] = v.w;                               \
        }                                                                           \
        _Pragma("unroll")                                                           \
        for (int fn = 0; fn < 8; fn++) {                                            \
            const uint2* p = (const uint2*)Bs + (((warp_n * 8 + fn) * 4 + (ks)) * 32 + lane); \
            uint2 v = *p;                                                           \
            (bbuf)[fn][0] = v.x; (bbuf)[fn][1] = v.y;                               \
        }                                                                           \
    } while (0)

    ISSUE(0); CP_COMMIT();
    ISSUE(1); CP_COMMIT();

    uint32_t a[2][4][4], b[2][8][2];

    for (int kt = 0; kt < 64; kt++) {
        CP_WAIT1();
        __syncthreads();
        if (kt + 2 < 64) ISSUE(kt + 2);
        CP_COMMIT();

        const float* As = sm + (kt % 3) * 8192;
        const float* Bs = As + 4096;

        LOAD_FRAG(0, a[0], b[0]);
#pragma unroll
        for (int ks = 0; ks < 4; ks++) {
            const int cur = ks & 1;
            if (ks < 3) LOAD_FRAG(ks + 1, a[cur ^ 1], b[cur ^ 1]);
#pragma unroll
            for (int fm = 0; fm < 4; fm++)
#pragma unroll
                for (int fn = 0; fn < 8; fn++)
                    mma8(c[fm][fn], a[cur][fm], b[cur][fn]);
        }
    }
#undef ISSUE
#undef LOAD_FRAG

    const int r0 = by * 128 + warp_m * 64 + (lane >> 2);
    const int c0 = bx * 128 + warp_n * 64 + (lane & 3) * 2;
#pragma unroll
    for (int fm = 0; fm < 4; fm++) {
#pragma unroll
        for (int fn = 0; fn < 8; fn++) {
            int row = r0 + fm * 16;
            int col = c0 + fn * 8;
            float2 v0 = make_float2(c[fm][fn][0], c[fm][fn][1]);
            float2 v1 = make_float2(c[fm][fn][2], c[fm][fn][3]);
            if (silu) {
                v0.x = v0.x / (1.f + expf(-v0.x));
                v0.y = v0.y / (1.f + expf(-v0.y));
                v1.x = v1.x / (1.f + expf(-v1.x));
                v1.y = v1.y / (1.f + expf(-v1.y));
            }
            *(float2*)(Co + (size_t)row * CDIM + col) = v0;
            *(float2*)(Co + (size_t)(row + 8) * CDIM + col) = v1;
        }
    }
}

// fused 4-projection GEMM: blockIdx.z picks operands (r,k,v,g)
__global__ __launch_bounds__(128) void k_gemm4(const float* __restrict__ Abase,
                                               const float* __restrict__ Wbase,
                                               float* __restrict__ o_r,
                                               float* __restrict__ o_k,
                                               float* __restrict__ o_v,
                                               float* __restrict__ o_g)
{
    extern __shared__ __align__(16) float sm[];
    const int z = blockIdx.z;
    const size_t MC = (size_t)MTOT * CDIM;
    const size_t WSLOT = (size_t)CDIM * CDIM;
    const int aslot = (z == 0) ? 2 : (z == 1) ? 0 : (z == 2) ? 1 : 3;
    float* Co = (z == 0) ? o_r : (z == 1) ? o_k : (z == 2) ? o_v : o_g;
    gemm_body(Abase + (size_t)aslot * MC, Wbase + (size_t)z * WSLOT, Co,
              blockIdx.x, blockIdx.y, z == 3, sm);
}

// single GEMM (output projection)
__global__ __launch_bounds__(128) void k_gemm1(const float* __restrict__ Ap,
                                               const float* __restrict__ Bp,
                                               float* __restrict__ Co)
{
    extern __shared__ __align__(16) float sm[];
    gemm_body(Ap, Bp, Co, blockIdx.x, blockIdx.y, false, sm);
}

// ---------------------------------------------------------------------------
// h = tanh(xd @ dw1)  [M,64]
// ---------------------------------------------------------------------------
__global__ __launch_bounds__(256) void k_decay_h(const float* __restrict__ dw1)
{
    __shared__ float As[64][33];
    __shared__ float Bs[32][64];
    const int tid = threadIdx.x;
    const int row0 = blockIdx.x * 64;
    const int tx = tid & 15, ty = tid >> 4;
    const int col0 = tx * 4, r0 = ty * 4;

    float acc[4][4];
#pragma unroll
    for (int i = 0; i < 4; i++)
#pragma unroll
        for (int j = 0; j < 4; j++) acc[i][j] = 0.f;

    for (int k0 = 0; k0 < CDIM; k0 += 32) {
        __syncthreads();
#pragma unroll
        for (int i = 0; i < 8; i++) {
            int lin = i * 256 + tid;
            int r = lin >> 5, kk = lin & 31;
            As[r][kk] = g_xd[(size_t)(row0 + r) * CDIM + k0 + kk];
        }
#pragma unroll
        for (int i = 0; i < 8; i++) {
            int lin = i * 256 + tid;
            int kk = lin >> 6, cc = lin & 63;
            Bs[kk][cc] = dw1[(size_t)(k0 + kk) * 64 + cc];
        }
        __syncthreads();
#pragma unroll
        for (int kk = 0; kk < 32; kk++) {
            float a[4], b[4];
#pragma unroll
            for (int i = 0; i < 4; i++) a[i] = As[r0 + i][kk];
#pragma unroll
            for (int j = 0; j < 4; j++) b[j] = Bs[kk][col0 + j];
#pragma unroll
            for (int i = 0; i < 4; i++)
#pragma unroll
                for (int j = 0; j < 4; j++)
                    acc[i][j] = fmaf(a[i], b[j], acc[i][j]);
        }
    }
#pragma unroll
    for (int i = 0; i < 4; i++)
#pragma unroll
        for (int j = 0; j < 4; j++)
            g_h[(size_t)(row0 + r0 + i) * 64 + col0 + j] = tanhf(acc[i][j]);
}

// ---------------------------------------------------------------------------
// w = exp(-exp(time_decay + h @ dw2))  [M,C]
// ---------------------------------------------------------------------------
__global__ __launch_bounds__(256) void k_decay_w(const float* __restrict__ dw2,
                                                 const float* __restrict__ tdec)
{
    __shared__ float hs[16][64];
    __shared__ float ws[32][256];
    const int tid = threadIdx.x;
    const int ct = blockIdx.x & 7;
    const int rt = blockIdx.x >> 3;
    const int row0 = rt * 16;
    const int c = ct * 256 + tid;

#pragma unroll
    for (int i = 0; i < 4; i++) {
        int lin = i * 256 + tid;
        int r = lin >> 6, e = lin & 63;
        hs[r][e] = g_h[(size_t)(row0 + r) * 64 + e];
    }
    float acc[16];
#pragma unroll
    for (int r = 0; r < 16; r++) acc[r] = 0.f;

    for (int ch = 0; ch < 2; ch++) {
        __syncthreads();
#pragma unroll
        for (int e = 0; e < 32; e++)
            ws[e][tid] = dw2[(size_t)(ch * 32 + e) * CDIM + c];
        __syncthreads();
#pragma unroll
        for (int e = 0; e < 32; e++) {
            float we = ws[e][tid];
#pragma unroll
            for (int r = 0; r < 16; r++)
                acc[r] = fmaf(hs[r][ch * 32 + e], we, acc[r]);
        }
    }
    float tb = tdec[c];
#pragma unroll
    for (int r = 0; r < 16; r++)
        g_w[(size_t)(row0 + r) * CDIM + c] = expf(-expf(tb + acc[r]));
}

// ---------------------------------------------------------------------------
// WKV scan. One block per (b,h). 256 thr = 64 value cols x 4 key splits.
// 16-deep cp.async ring, prefetch distance 8, FOUR timesteps per barrier.
// Safety: writes at iter t hit slots (t+8..t+11)&15 = t-8..t-5, read during
// iter t-8 and fenced by the barrier executed at iter t-4.
// ---------------------------------------------------------------------------
__global__ __launch_bounds__(256) void k_wkv(const float* __restrict__ faaaa)
{
    __shared__ float sh[16][4][64];
    const int tid = threadIdx.x;
    const int bh = blockIdx.x;
    const int b = bh >> 5, h = bh & 31;
    const int m = tid >> 2, s = tid & 3;
    const int n0 = s << 4;
    const int colbase = h << 6;

    const int which = tid >> 6;
    const int idx = tid & 63;
    const float* srcs[4] = {g_r, g_k, g_v, g_w};
    const float* myp = srcs[which] + (size_t)b * TSEQ * CDIM + colbase + idx;
    const uint32_t mydst = su32(&sh[0][which][idx]);   // slot stride 1024B

    unsigned long long u2[8];
    {
        const unsigned long long* up = (const unsigned long long*)(faaaa + colbase + n0);
#pragma unroll
        for (int i = 0; i < 8; i++) u2[i] = up[i];
    }
    unsigned long long st[8];
#pragma unroll
    for (int i = 0; i < 8; i++) st[i] = 0ull;

    // prologue: prefetch steps 0..7 (one commit group each)
#pragma unroll
    for (int d = 0; d < 8; d++) {
        cp4(mydst + (uint32_t)d * 1024, myp + (size_t)d * CDIM);
        CP_COMMIT();
    }

    float* outp = g_a + (size_t)b * TSEQ * CDIM + colbase + m;

    for (int t = 0; t < TSEQ; t += 4) {
#pragma unroll
        for (int q = 0; q < 4; q++) {
            if (t + 8 + q < TSEQ)
                cp4(mydst + (uint32_t)((t + 8 + q) & 15) * 1024,
                    myp + (size_t)(t + 8 + q) * CDIM);
            CP_COMMIT();
        }
        CP_WAIT8();            // slots t..t+3 complete
        __syncthreads();

#pragma unroll
        for (int step = 0; step < 4; step++) {
            const int slot = (t + step) & 15;
            float vm = sh[slot][2][m];
            unsigned long long v2 = f2_pack(vm, vm);
            const unsigned long long* rp = (const unsigned long long*)&sh[slot][0][n0];
            const unsigned long long* kp = (const unsigned long long*)&sh[slot][1][n0];
            const unsigned long long* wp = (const unsigned long long*)&sh[slot][3][n0];

            unsigned long long acc2 = 0ull;
#pragma unroll
            for (int i = 0; i < 8; i++) {
                unsigned long long kv  = f2_mul(kp[i], v2);
                unsigned long long tmp = f2_fma(u2[i], kv, st[i]);
                acc2 = f2_fma(rp[i], tmp, acc2);
                st[i] = f2_fma(wp[i], st[i], kv);
            }
            float lo, hi;
            f2_unpack(acc2, lo, hi);
            float acc = lo + hi;
            acc += __shfl_xor_sync(0xffffffffu, acc, 1);
            acc += __shfl_xor_sync(0xffffffffu, acc, 2);
            if (s == 0) outp[(size_t)(t + step) * CDIM] = acc;
        }
    }
}

// ---------------------------------------------------------------------------
// GroupNorm * ln_w + ln_b, * gate -> fragment-packed tf32 g_ypack
// ---------------------------------------------------------------------------
__global__ __launch_bounds__(1024) void k_gnmul(const float* __restrict__ lnw,
                                                const float* __restrict__ lnb)
{
    const int row = blockIdx.x;
    const int wp = threadIdx.x >> 5;
    const int l = threadIdx.x & 31;
    const int c0 = wp * 64 + l;
    const size_t base = (size_t)row * CDIM;

    float a0 = g_a[base + c0];
    float a1 = g_a[base + c0 + 32];
    float s = a0 + a1;
    float q = a0 * a0 + a1 * a1;
#pragma unroll
    for (int off = 16; off; off >>= 1) {
        s += __shfl_xor_sync(0xffffffffu, s, off);
        q += __shfl_xor_sync(0xffffffffu, q, off);
    }
    float mean = s * (1.f / 64.f);
    float var = q * (1.f / 64.f) - mean * mean;
    float rstd = rsqrtf(var + GN_EPS);
    float y0 = (a0 - mean) * rstd * lnw[c0] + lnb[c0];
    float y1 = (a1 - mean) * rstd * lnw[c0 + 32] + lnb[c0 + 32];
    g_ypack[packA_idx(row, c0)]      = tf32r(y0 * g_gt[base + c0]);
    g_ypack[packA_idx(row, c0 + 32)] = tf32r(y1 * g_gt[base + c0 + 32]);
}

// ---------------------------------------------------------------------------
// Launch: R13 fork/join graph (wkv runs ALONE — never co-schedule with it)
//   s2: packB  (joined before gemm4)
//   main: prep_t5 -> lerp5 -> gemm4 -> [join decay] -> wkv -> gnmul -> gemm1
//   s1: decay_h -> decay_w (forked after lerp5, joined before wkv)
// ---------------------------------------------------------------------------
extern "C" void kernel_launch(void* const* d_in, const int* in_sizes, int n_in,
                              void* d_out, int out_size)
{
    const float* x     = (const float*)d_in[0];
    const float* maa_x = (const float*)d_in[1];
    const float* maa_w = (const float*)d_in[2];
    const float* maa_k = (const float*)d_in[3];
    const float* maa_v = (const float*)d_in[4];
    const float* maa_r = (const float*)d_in[5];
    const float* maa_g = (const float*)d_in[6];
    const float* w1    = (const float*)d_in[7];
    const float* w2    = (const float*)d_in[8];
    const float* tdec  = (const float*)d_in[9];
    const float* dw1   = (const float*)d_in[10];
    const float* dw2   = (const float*)d_in[11];
    const float* u     = (const float*)d_in[12];
    const float* w_r   = (const float*)d_in[13];
    const float* w_k   = (const float*)d_in[14];
    const float* w_v   = (const float*)d_in[15];
    const float* w_g   = (const float*)d_in[16];
    const float* w_o   = (const float*)d_in[17];
    const float* lnw   = (const float*)d_in[18];
    const float* lnb   = (const float*)d_in[19];
    float* out = (float*)d_out;

    float *p_apack, *p_ypack, *p_wpack, *p_r, *p_k, *p_v, *p_g;
    cudaGetSymbolAddress((void**)&p_apack, g_apack);
    cudaGetSymbolAddress((void**)&p_ypack, g_ypack);
    cudaGetSymbolAddress((void**)&p_wpack, g_wpack);
    cudaGetSymbolAddress((void**)&p_r, g_r);
    cudaGetSymbolAddress((void**)&p_k, g_k);
    cudaGetSymbolAddress((void**)&p_v, g_v);
    cudaGetSymbolAddress((void**)&p_g, g_gt);

    const size_t WSLOT = (size_t)CDIM * CDIM;
    const int GEMM_SMEM = 3 * 32768;   // 98304 -> 2 CTAs/SM

    cudaFuncSetAttribute(k_gemm4, cudaFuncAttributeMaxDynamicSharedMemorySize, GEMM_SMEM);
    cudaFuncSetAttribute(k_gemm1, cudaFuncAttributeMaxDynamicSharedMemorySize, GEMM_SMEM);

    // fork s2 from main stream, run weight packing there
    cudaEventRecord(g_env.evRoot, 0);
    cudaStreamWaitEvent(g_env.s2, g_env.evRoot, 0);
    dim3 pg(16384, 5);
    k_packB_all<<<pg, 256, 0, g_env.s2>>>(w_r, w_k, w_v, w_g, w_o, p_wpack);
    cudaEventRecord(g_env.ePack, g_env.s2);

    // main: t5 -> lerp5
    k_prep_t5<<<MTOT / 64, 256>>>(x, maa_x, w1);
    k_lerp5<<<(MTOT / 16) * 8, 256>>>(x, w2, maa_w, maa_k, maa_v, maa_r, maa_g);

    // fork s1 after lerp5: decay chain (independent of gemm4)
    cudaEventRecord(g_env.eLerp, 0);
    cudaStreamWaitEvent(g_env.s1, g_env.eLerp, 0);
    k_decay_h<<<MTOT / 64, 256, 0, g_env.s1>>>(dw1);
    k_decay_w<<<(MTOT / 16) * 8, 256, 0, g_env.s1>>>(dw2, tdec);
    cudaEventRecord(g_env.eDecay, g_env.s1);

    // main: join packB, run the big fused GEMM
    cudaStreamWaitEvent(0, g_env.ePack, 0);
    dim3 gg4(CDIM / 128, MTOT / 128, 4);
    k_gemm4<<<gg4, 128, GEMM_SMEM>>>(p_apack, p_wpack, p_r, p_k, p_v, p_g);

    // main: join decay chain, then scan -> gn -> output proj
    cudaStreamWaitEvent(0, g_env.eDecay, 0);
    k_wkv<<<BB * HHEADS, 256>>>(u);

    k_gnmul<<<MTOT, 1024>>>(lnw, lnb);

    dim3 gg(CDIM / 128, MTOT / 128);
    k_gemm1<<<gg, 128, GEMM_SMEM>>>(p_ypack, p_wpack + 4 * WSLOT, out);
}

// round 17
// speedup vs baseline: 1.2907x; 1.0012x over previous
#include <cuda_runtime.h>
#include <cuda_bf16.h>
#include <cstddef>
#include <cstdint>

// Problem constants
#define BB    4
#define TSEQ  2048
#define CDIM  2048
#define MTOT  8192          // BB*TSEQ
#define HHEADS 32
#define NSZ   64
#define GN_EPS 6.4e-4f      // 1e-5 * 8^2

// ---------------------------------------------------------------------------
// Scratch
// ---------------------------------------------------------------------------
__device__ float g_apack[4ull * MTOT * CDIM];   // fragment-packed tf32: xk,xv,xr,xg
__device__ float g_ypack[(size_t)MTOT * CDIM];  // fragment-packed gn*gate
__device__ float g_wpack[5ull * CDIM * CDIM];   // fragment-packed weights: r,k,v,g,o
__device__ float g_xd  [(size_t)MTOT * CDIM];
__device__ float g_t5  [MTOT * 160];
__device__ float g_r   [(size_t)MTOT * CDIM];
__device__ float g_k   [(size_t)MTOT * CDIM];
__device__ float g_v   [(size_t)MTOT * CDIM];
__device__ float g_gt  [(size_t)MTOT * CDIM];
__device__ float g_w   [(size_t)MTOT * CDIM];
__device__ float g_h   [MTOT * 64];
__device__ float g_a   [(size_t)MTOT * CDIM];

// ---------------------------------------------------------------------------
// side streams + events for graph-captured fork/join
// ---------------------------------------------------------------------------
struct StreamEnv {
    cudaStream_t s1 = nullptr, s2 = nullptr;
    cudaEvent_t evRoot = nullptr, ePack = nullptr, eLerp = nullptr, eDecay = nullptr;
    StreamEnv() {
        cudaStreamCreateWithFlags(&s1, cudaStreamNonBlocking);
        cudaStreamCreateWithFlags(&s2, cudaStreamNonBlocking);
        cudaEventCreateWithFlags(&evRoot, cudaEventDisableTiming);
        cudaEventCreateWithFlags(&ePack, cudaEventDisableTiming);
        cudaEventCreateWithFlags(&eLerp, cudaEventDisableTiming);
        cudaEventCreateWithFlags(&eDecay, cudaEventDisableTiming);
    }
};
static StreamEnv g_env;

// ---------------------------------------------------------------------------
// helpers
// ---------------------------------------------------------------------------
__device__ __forceinline__ unsigned long long f2_pack(float lo, float hi) {
    unsigned long long r;
    asm("mov.b64 %0, {%1, %2};" : "=l"(r) : "f"(lo), "f"(hi));
    return r;
}
__device__ __forceinline__ void f2_unpack(unsigned long long v, float& lo, float& hi) {
    asm("mov.b64 {%0, %1}, %2;" : "=f"(lo), "=f"(hi) : "l"(v));
}
__device__ __forceinline__ unsigned long long f2_fma(unsigned long long a,
                                                     unsigned long long b,
                                                     unsigned long long c) {
    unsigned long long d;
    asm("fma.rn.f32x2 %0, %1, %2, %3;" : "=l"(d) : "l"(a), "l"(b), "l"(c));
    return d;
}
__device__ __forceinline__ unsigned long long f2_mul(unsigned long long a,
                                                     unsigned long long b) {
    unsigned long long d;
    asm("mul.rn.f32x2 %0, %1, %2;" : "=l"(d) : "l"(a), "l"(b));
    return d;
}
__device__ __forceinline__ float tf32r(float x) {
    uint32_t u;
    asm("cvt.rna.tf32.f32 %0, %1;" : "=r"(u) : "f"(x));
    return __uint_as_float(u);
}
__device__ __forceinline__ uint32_t su32(const void* p) {
    uint32_t a;
    asm("{ .reg .u64 t; cvta.to.shared.u64 t, %1; cvt.u32.u64 %0, t; }" : "=r"(a) : "l"(p));
    return a;
}
__device__ __forceinline__ void cp16(uint32_t dst, const void* src) {
    asm volatile("cp.async.cg.shared.global [%0], [%1], 16;" :: "r"(dst), "l"(src));
}
__device__ __forceinline__ void cp4(uint32_t dst, const void* src) {
    asm volatile("cp.async.ca.shared.global [%0], [%1], 4;" :: "r"(dst), "l"(src));
}
#define CP_COMMIT() asm volatile("cp.async.commit_group;" ::: "memory")
#define CP_WAIT1()  asm volatile("cp.async.wait_group 1;" ::: "memory")
#define CP_WAIT8()  asm volatile("cp.async.wait_group 8;" ::: "memory")

__device__ __forceinline__ void mma8(float* c, const uint32_t* a, const uint32_t* b) {
    asm volatile(
        "mma.sync.aligned.m16n8k8.row.col.f32.tf32.tf32.f32 "
        "{%0,%1,%2,%3}, {%4,%5,%6,%7}, {%8,%9}, {%0,%1,%2,%3};"
        : "+f"(c[0]), "+f"(c[1]), "+f"(c[2]), "+f"(c[3])
        : "r"(a[0]), "r"(a[1]), "r"(a[2]), "r"(a[3]), "r"(b[0]), "r"(b[1]));
}

// -------- fragment-packed global layouts --------
__device__ __forceinline__ size_t packA_idx(int m, int k) {
    int r = m & 15, c = k & 7;
    int lane = ((r & 7) << 2) | (c & 3);
    int i = (r >> 3) | ((c >> 2) << 1);
    int atom = (((m >> 4) & 7) << 2) | ((k >> 3) & 3);
    size_t tile = ((size_t)(m >> 7) << 6) + (size_t)(k >> 5);
    return (tile << 12) + (size_t)((atom << 7) + (lane << 2) + i);
}
__device__ __forceinline__ size_t packB_idx(int n, int k) {
    int lane = ((n & 7) << 2) | (k & 3);
    int j = (k >> 2) & 1;
    int atom = (((n >> 3) & 31) << 2) | ((k >> 3) & 3);
    size_t tile = ((size_t)(n >> 8) << 6) + (size_t)(k >> 5);
    return (tile << 13) + (size_t)((atom << 6) + (lane << 1) + j);
}

// ---------------------------------------------------------------------------
// pack all 5 weights
// ---------------------------------------------------------------------------
__global__ __launch_bounds__(256) void k_packB_all(const float* __restrict__ w0,
                                                   const float* __restrict__ w1,
                                                   const float* __restrict__ w2,
                                                   const float* __restrict__ w3,
                                                   const float* __restrict__ w4,
                                                   float* __restrict__ o)
{
    const float* ws[5] = {w0, w1, w2, w3, w4};
    const float* w = ws[blockIdx.y];
    float* oo = o + (size_t)blockIdx.y * CDIM * CDIM;
    int g = blockIdx.x * 256 + threadIdx.x;
    int n = g >> 11, k = g & 2047;
    oo[packB_idx(n, k)] = tf32r(w[g]);
}

// ---------------------------------------------------------------------------
// t5 = tanh( (x + (shift(x)-x)*maa_x) @ W1 )   [M,160]
// ---------------------------------------------------------------------------
__global__ __launch_bounds__(256) void k_prep_t5(const float* __restrict__ x,
                                                 const float* __restrict__ maa_x,
                                                 const float* __restrict__ w1)
{
    __shared__ float As[64][33];
    __shared__ float Bs[32][160];
    const int tid = threadIdx.x;
    const int row0 = blockIdx.x * 64;
    const int tx = tid & 31, ty = tid >> 5;
    const int col0 = tx * 5, r0 = ty * 8;

    float acc[8][5];
#pragma unroll
    for (int i = 0; i < 8; i++)
#pragma unroll
        for (int j = 0; j < 5; j++) acc[i][j] = 0.f;

    for (int k0 = 0; k0 < CDIM; k0 += 32) {
        __syncthreads();
#pragma unroll
        for (int i = 0; i < 8; i++) {
            int lin = i * 256 + tid;
            int r = lin >> 5, kk = lin & 31;
            int gr = row0 + r, gc = k0 + kk;
            float xv = x[(size_t)gr * CDIM + gc];
            float xp = (gr & (TSEQ - 1)) ? x[(size_t)(gr - 1) * CDIM + gc] : 0.f;
            As[r][kk] = xv + (xp - xv) * maa_x[gc];
        }
#pragma unroll
        for (int i = 0; i < 20; i++) {
            int lin = i * 256 + tid;
            int kk = lin / 160, c = lin - kk * 160;
            Bs[kk][c] = w1[(size_t)(k0 + kk) * 160 + c];
        }
        __syncthreads();
#pragma unroll
        for (int kk = 0; kk < 32; kk++) {
            float a[8], b[5];
#pragma unroll
            for (int i = 0; i < 8; i++) a[i] = As[r0 + i][kk];
#pragma unroll
            for (int j = 0; j < 5; j++) b[j] = Bs[kk][col0 + j];
#pragma unroll
            for (int i = 0; i < 8; i++)
#pragma unroll
                for (int j = 0; j < 5; j++)
                    acc[i][j] = fmaf(a[i], b[j], acc[i][j]);
        }
    }
#pragma unroll
    for (int i = 0; i < 8; i++)
#pragma unroll
        for (int j = 0; j < 5; j++)
            g_t5[(size_t)(row0 + r0 + i) * 160 + col0 + j] = tanhf(acc[i][j]);
}

// ---------------------------------------------------------------------------
// for f in 0..4: lerp_f = x + xx*(maa_f + t5[:,f,:] @ w2[f])   (R5 version)
// ---------------------------------------------------------------------------
__global__ __launch_bounds__(256) void k_lerp5(const float* __restrict__ x,
                                               const float* __restrict__ w2,
                                               const float* __restrict__ maa_w,
                                               const float* __restrict__ maa_k,
                                               const float* __restrict__ maa_v,
                                               const float* __restrict__ maa_r,
                                               const float* __restrict__ maa_g)
{
    __shared__ float t5s[16][160];
    __shared__ float w2s[32][256];
    const int tid = threadIdx.x;
    const int ct = blockIdx.x & 7;
    const int rt = blockIdx.x >> 3;
    const int row0 = rt * 16;
    const int c = ct * 256 + tid;
    const size_t MC = (size_t)MTOT * CDIM;

#pragma unroll
    for (int i = 0; i < 10; i++) {
        int lin = i * 256 + tid;
        int r = lin / 160, e = lin - r * 160;
        t5s[r][e] = g_t5[(size_t)(row0 + r) * 160 + e];
    }
    float xv[16], xxv[16];
#pragma unroll
    for (int r = 0; r < 16; r++) {
        int gr = row0 + r;
        float v = x[(size_t)gr * CDIM + c];
        float p = (gr & (TSEQ - 1)) ? x[(size_t)(gr - 1) * CDIM + c] : 0.f;
        xv[r] = v; xxv[r] = p - v;
    }
    const float* maas[5] = {maa_w, maa_k, maa_v, maa_r, maa_g};

    for (int f = 0; f < 5; f++) {
        __syncthreads();
#pragma unroll
        for (int e = 0; e < 32; e++)
            w2s[e][tid] = w2[(size_t)(f * 32 + e) * CDIM + c];
        __syncthreads();

        float acc[16];
#pragma unroll
        for (int r = 0; r < 16; r++) acc[r] = 0.f;
#pragma unroll
        for (int e = 0; e < 32; e++) {
            float we = w2s[e][tid];
#pragma unroll
            for (int r = 0; r < 16; r++)
                acc[r] = fmaf(t5s[r][f * 32 + e], we, acc[r]);
        }
        float mb = maas[f][c];
        if (f == 0) {
#pragma unroll
            for (int r = 0; r < 16; r++)
                g_xd[(size_t)(row0 + r) * CDIM + c] = xv[r] + xxv[r] * (mb + acc[r]);
        } else {
            float* outp = g_apack + (size_t)(f - 1) * MC;
#pragma unroll
            for (int r = 0; r < 16; r++)
                outp[packA_idx(row0 + r, c)] = tf32r(xv[r] + xxv[r] * (mb + acc[r]));
        }
    }
}

// ---------------------------------------------------------------------------
// tf32 mma.sync GEMM body (R11 known-best)
// ---------------------------------------------------------------------------
__device__ __forceinline__ void gemm_body(const float* __restrict__ Ap,
                                          const float* __restrict__ Bp,
                                          float* __restrict__ Co,
                                          int bx, int by, bool silu,
                                          float* sm)
{
    const int tid = threadIdx.x;
    const int lane = tid & 31, wid = tid >> 5;
    const int warp_m = wid >> 1, warp_n = wid & 1;

    const float* Ag = Ap + ((size_t)by << 6 << 12);
    const float* Bg = Bp + ((size_t)(bx >> 1) << 6 << 13)
                         + (size_t)(bx & 1) * 4096;
    const uint32_t sbase = su32(sm);

    float c[4][8][4];
#pragma unroll
    for (int fm = 0; fm < 4; fm++)
#pragma unroll
        for (int fn = 0; fn < 8; fn++)
#pragma unroll
            for (int i = 0; i < 4; i++) c[fm][fn][i] = 0.f;

#define ISSUE(kt)                                                                  \
    do {                                                                           \
        uint32_t d = sbase + ((kt) % 3) * 32768;                                   \
        const float4* a4 = (const float4*)(Ag + ((size_t)(kt) << 12));             \
        const float4* b4 = (const float4*)(Bg + ((size_t)(kt) << 13));             \
        _Pragma("unroll")                                                          \
        for (int i = 0; i < 8; i++)                                                \
            cp16(d + (uint32_t)(tid + i * 128) * 16, a4 + tid + i * 128);          \
        _Pragma("unroll")                                                          \
        for (int i = 0; i < 8; i++)                                                \
            cp16(d + 16384 + (uint32_t)(tid + i * 128) * 16, b4 + tid + i * 128);  \
    } while (0)

#define LOAD_FRAG(ks, abuf, bbuf)                                                   \
    do {                                                                            \
        _Pragma("unroll")                                                           \
        for (int fm = 0; fm < 4; fm++) {                                            \
            const uint4* p = (const uint4*)As + (((warp_m * 4 + fm) * 4 + (ks)) * 32 + lane); \
            uint4 v = *p;                                                           \
            (abuf)[fm][0] = v.x; (abuf)[fm][1] = v.y;                               \
            (abuf)[fm][2] = v.z; (abuf)[fm][3] = v.w;                               \
        }                                                                           \
        _Pragma("unroll")                                                           \
        for (int fn = 0; fn < 8; fn++) {                                            \
            const uint2* p = (const uint2*)Bs + (((warp_n * 8 + fn) * 4 + (ks)) * 32 + lane); \
            uint2 v = *p;                                                           \
            (bbuf)[fn][0] = v.x; (bbuf)[fn][1] = v.y;                               \
        }                                                                           \
    } while (0)

    ISSUE(0); CP_COMMIT();
    ISSUE(1); CP_COMMIT();

    uint32_t a[2][4][4], b[2][8][2];

    for (int kt = 0; kt < 64; kt++) {
        CP_WAIT1();
        __syncthreads();
        if (kt + 2 < 64) ISSUE(kt + 2);
        CP_COMMIT();

        const float* As = sm + (kt % 3) * 8192;
        const float* Bs = As + 4096;

        LOAD_FRAG(0, a[0], b[0]);
#pragma unroll
        for (int ks = 0; ks < 4; ks++) {
            const int cur = ks & 1;
            if (ks < 3) LOAD_FRAG(ks + 1, a[cur ^ 1], b[cur ^ 1]);
#pragma unroll
            for (int fm = 0; fm < 4; fm++)
#pragma unroll
                for (int fn = 0; fn < 8; fn++)
                    mma8(c[fm][fn], a[cur][fm], b[cur][fn]);
        }
    }
#undef ISSUE
#undef LOAD_FRAG

    const int r0 = by * 128 + warp_m * 64 + (lane >> 2);
    const int c0 = bx * 128 + warp_n * 64 + (lane & 3) * 2;
#pragma unroll
    for (int fm = 0; fm < 4; fm++) {
#pragma unroll
        for (int fn = 0; fn < 8; fn++) {
            int row = r0 + fm * 16;
            int col = c0 + fn * 8;
            float2 v0 = make_float2(c[fm][fn][0], c[fm][fn][1]);
            float2 v1 = make_float2(c[fm][fn][2], c[fm][fn][3]);
            if (silu) {
                v0.x = v0.x / (1.f + expf(-v0.x));
                v0.y = v0.y / (1.f + expf(-v0.y));
                v1.x = v1.x / (1.f + expf(-v1.x));
                v1.y = v1.y / (1.f + expf(-v1.y));
            }
            *(float2*)(Co + (size_t)row * CDIM + col) = v0;
            *(float2*)(Co + (size_t)(row + 8) * CDIM + col) = v1;
        }
    }
}

// fused 4-projection GEMM: blockIdx.z picks operands (r,k,v,g)
__global__ __launch_bounds__(128) void k_gemm4(const float* __restrict__ Abase,
                                               const float* __restrict__ Wbase,
                                               float* __restrict__ o_r,
                                               float* __restrict__ o_k,
                                               float* __restrict__ o_v,
                                               float* __restrict__ o_g)
{
    extern __shared__ __align__(16) float sm[];
    const int z = blockIdx.z;
    const size_t MC = (size_t)MTOT * CDIM;
    const size_t WSLOT = (size_t)CDIM * CDIM;
    const int aslot = (z == 0) ? 2 : (z == 1) ? 0 : (z == 2) ? 1 : 3;
    float* Co = (z == 0) ? o_r : (z == 1) ? o_k : (z == 2) ? o_v : o_g;
    gemm_body(Abase + (size_t)aslot * MC, Wbase + (size_t)z * WSLOT, Co,
              blockIdx.x, blockIdx.y, z == 3, sm);
}

// single GEMM (output projection)
__global__ __launch_bounds__(128) void k_gemm1(const float* __restrict__ Ap,
                                               const float* __restrict__ Bp,
                                               float* __restrict__ Co)
{
    extern __shared__ __align__(16) float sm[];
    gemm_body(Ap, Bp, Co, blockIdx.x, blockIdx.y, false, sm);
}

// ---------------------------------------------------------------------------
// h = tanh(xd @ dw1)  [M,64]
// ---------------------------------------------------------------------------
__global__ __launch_bounds__(256) void k_decay_h(const float* __restrict__ dw1)
{
    __shared__ float As[64][33];
    __shared__ float Bs[32][64];
    const int tid = threadIdx.x;
    const int row0 = blockIdx.x * 64;
    const int tx = tid & 15, ty = tid >> 4;
    const int col0 = tx * 4, r0 = ty * 4;

    float acc[4][4];
#pragma unroll
    for (int i = 0; i < 4; i++)
#pragma unroll
        for (int j = 0; j < 4; j++) acc[i][j] = 0.f;

    for (int k0 = 0; k0 < CDIM; k0 += 32) {
        __syncthreads();
#pragma unroll
        for (int i = 0; i < 8; i++) {
            int lin = i * 256 + tid;
            int r = lin >> 5, kk = lin & 31;
            As[r][kk] = g_xd[(size_t)(row0 + r) * CDIM + k0 + kk];
        }
#pragma unroll
        for (int i = 0; i < 8; i++) {
            int lin = i * 256 + tid;
            int kk = lin >> 6, cc = lin & 63;
            Bs[kk][cc] = dw1[(size_t)(k0 + kk) * 64 + cc];
        }
        __syncthreads();
#pragma unroll
        for (int kk = 0; kk < 32; kk++) {
            float a[4], b[4];
#pragma unroll
            for (int i = 0; i < 4; i++) a[i] = As[r0 + i][kk];
#pragma unroll
            for (int j = 0; j < 4; j++) b[j] = Bs[kk][col0 + j];
#pragma unroll
            for (int i = 0; i < 4; i++)
#pragma unroll
                for (int j = 0; j < 4; j++)
                    acc[i][j] = fmaf(a[i], b[j], acc[i][j]);
        }
    }
#pragma unroll
    for (int i = 0; i < 4; i++)
#pragma unroll
        for (int j = 0; j < 4; j++)
            g_h[(size_t)(row0 + r0 + i) * 64 + col0 + j] = tanhf(acc[i][j]);
}

// ---------------------------------------------------------------------------
// w = exp(-exp(time_decay + h @ dw2))  [M,C]
// ---------------------------------------------------------------------------
__global__ __launch_bounds__(256) void k_decay_w(const float* __restrict__ dw2,
                                                 const float* __restrict__ tdec)
{
    __shared__ float hs[16][64];
    __shared__ float ws[32][256];
    const int tid = threadIdx.x;
    const int ct = blockIdx.x & 7;
    const int rt = blockIdx.x >> 3;
    const int row0 = rt * 16;
    const int c = ct * 256 + tid;

#pragma unroll
    for (int i = 0; i < 4; i++) {
        int lin = i * 256 + tid;
        int r = lin >> 6, e = lin & 63;
        hs[r][e] = g_h[(size_t)(row0 + r) * 64 + e];
    }
    float acc[16];
#pragma unroll
    for (int r = 0; r < 16; r++) acc[r] = 0.f;

    for (int ch = 0; ch < 2; ch++) {
        __syncthreads();
#pragma unroll
        for (int e = 0; e < 32; e++)
            ws[e][tid] = dw2[(size_t)(ch * 32 + e) * CDIM + c];
        __syncthreads();
#pragma unroll
        for (int e = 0; e < 32; e++) {
            float we = ws[e][tid];
#pragma unroll
            for (int r = 0; r < 16; r++)
                acc[r] = fmaf(hs[r][ch * 32 + e], we, acc[r]);
        }
    }
    float tb = tdec[c];
#pragma unroll
    for (int r = 0; r < 16; r++)
        g_w[(size_t)(row0 + r) * CDIM + c] = expf(-expf(tb + acc[r]));
}

// ---------------------------------------------------------------------------
// WKV scan. One block per (b,h). 256 thr = 64 value cols x 4 key splits.
// 16-deep cp.async ring, prefetch distance 8, FOUR timesteps per barrier.
// Safety: writes at iter t hit slots (t+8..t+11)&15 = t-8..t-5, read during
// iter t-8 and fenced by the barrier executed at iter t-4.
// ---------------------------------------------------------------------------
__global__ __launch_bounds__(256) void k_wkv(const float* __restrict__ faaaa)
{
    __shared__ float sh[16][4][64];
    const int tid = threadIdx.x;
    const int bh = blockIdx.x;
    const int b = bh >> 5, h = bh & 31;
    const int m = tid >> 2, s = tid & 3;
    const int n0 = s << 4;
    const int colbase = h << 6;

    const int which = tid >> 6;
    const int idx = tid & 63;
    const float* srcs[4] = {g_r, g_k, g_v, g_w};
    const float* myp = srcs[which] + (size_t)b * TSEQ * CDIM + colbase + idx;
    const uint32_t mydst = su32(&sh[0][which][idx]);   // slot stride 1024B

    unsigned long long u2[8];
    {
        const unsigned long long* up = (const unsigned long long*)(faaaa + colbase + n0);
#pragma unroll
        for (int i = 0; i < 8; i++) u2[i] = up[i];
    }
    unsigned long long st[8];
#pragma unroll
    for (int i = 0; i < 8; i++) st[i] = 0ull;

    // prologue: prefetch steps 0..7 (one commit group each)
#pragma unroll
    for (int d = 0; d < 8; d++) {
        cp4(mydst + (uint32_t)d * 1024, myp + (size_t)d * CDIM);
        CP_COMMIT();
    }

    float* outp = g_a + (size_t)b * TSEQ * CDIM + colbase + m;

    for (int t = 0; t < TSEQ; t += 4) {
#pragma unroll
        for (int q = 0; q < 4; q++) {
            if (t + 8 + q < TSEQ)
                cp4(mydst + (uint32_t)((t + 8 + q) & 15) * 1024,
                    myp + (size_t)(t + 8 + q) * CDIM);
            CP_COMMIT();
        }
        CP_WAIT8();            // slots t..t+3 complete
        __syncthreads();

#pragma unroll
        for (int step = 0; step < 4; step++) {
            const int slot = (t + step) & 15;
            float vm = sh[slot][2][m];
            unsigned long long v2 = f2_pack(vm, vm);
            const unsigned long long* rp = (const unsigned long long*)&sh[slot][0][n0];
            const unsigned long long* kp = (const unsigned long long*)&sh[slot][1][n0];
            const unsigned long long* wp = (const unsigned long long*)&sh[slot][3][n0];

            unsigned long long acc2 = 0ull;
#pragma unroll
            for (int i = 0; i < 8; i++) {
                unsigned long long kv  = f2_mul(kp[i], v2);
                unsigned long long tmp = f2_fma(u2[i], kv, st[i]);
                acc2 = f2_fma(rp[i], tmp, acc2);
                st[i] = f2_fma(wp[i], st[i], kv);
            }
            float lo, hi;
            f2_unpack(acc2, lo, hi);
            float acc = lo + hi;
            acc += __shfl_xor_sync(0xffffffffu, acc, 1);
            acc += __shfl_xor_sync(0xffffffffu, acc, 2);
            if (s == 0) outp[(size_t)(t + step) * CDIM] = acc;
        }
    }
}

// ---------------------------------------------------------------------------
// GroupNorm * ln_w + ln_b, * gate -> fragment-packed tf32 g_ypack
// ---------------------------------------------------------------------------
__global__ __launch_bounds__(1024) void k_gnmul(const float* __restrict__ lnw,
                                                const float* __restrict__ lnb)
{
    const int row = blockIdx.x;
    const int wp = threadIdx.x >> 5;
    const int l = threadIdx.x & 31;
    const int c0 = wp * 64 + l;
    const size_t base = (size_t)row * CDIM;

    float a0 = g_a[base + c0];
    float a1 = g_a[base + c0 + 32];
    float s = a0 + a1;
    float q = a0 * a0 + a1 * a1;
#pragma unroll
    for (int off = 16; off; off >>= 1) {
        s += __shfl_xor_sync(0xffffffffu, s, off);
        q += __shfl_xor_sync(0xffffffffu, q, off);
    }
    float mean = s * (1.f / 64.f);
    float var = q * (1.f / 64.f) - mean * mean;
    float rstd = rsqrtf(var + GN_EPS);
    float y0 = (a0 - mean) * rstd * lnw[c0] + lnb[c0];
    float y1 = (a1 - mean) * rstd * lnw[c0 + 32] + lnb[c0 + 32];
    g_ypack[packA_idx(row, c0)]      = tf32r(y0 * g_gt[base + c0]);
    g_ypack[packA_idx(row, c0 + 32)] = tf32r(y1 * g_gt[base + c0 + 32]);
}

// ---------------------------------------------------------------------------
// Launch: R13 fork/join graph (wkv runs ALONE — never co-schedule with it)
//   s2: packB  (joined before gemm4)
//   main: prep_t5 -> lerp5 -> gemm4 -> [join decay] -> wkv -> gnmul -> gemm1
//   s1: decay_h -> decay_w (forked after lerp5, joined before wkv)
// ---------------------------------------------------------------------------
extern "C" void kernel_launch(void* const* d_in, const int* in_sizes, int n_in,
                              void* d_out, int out_size)
{
    const float* x     = (const float*)d_in[0];
    const float* maa_x = (const float*)d_in[1];
    const float* maa_w = (const float*)d_in[2];
    const float* maa_k = (const float*)d_in[3];
    const float* maa_v = (const float*)d_in[4];
    const float* maa_r = (const float*)d_in[5];
    const float* maa_g = (const float*)d_in[6];
    const float* w1    = (const float*)d_in[7];
    const float* w2    = (const float*)d_in[8];
    const float* tdec  = (const float*)d_in[9];
    const float* dw1   = (const float*)d_in[10];
    const float* dw2   = (const float*)d_in[11];
    const float* u     = (const float*)d_in[12];
    const float* w_r   = (const float*)d_in[13];
    const float* w_k   = (const float*)d_in[14];
    const float* w_v   = (const float*)d_in[15];
    const float* w_g   = (const float*)d_in[16];
    const float* w_o   = (const float*)d_in[17];
    const float* lnw   = (const float*)d_in[18];
    const float* lnb   = (const float*)d_in[19];
    float* out = (float*)d_out;

    float *p_apack, *p_ypack, *p_wpack, *p_r, *p_k, *p_v, *p_g;
    cudaGetSymbolAddress((void**)&p_apack, g_apack);
    cudaGetSymbolAddress((void**)&p_ypack, g_ypack);
    cudaGetSymbolAddress((void**)&p_wpack, g_wpack);
    cudaGetSymbolAddress((void**)&p_r, g_r);
    cudaGetSymbolAddress((void**)&p_k, g_k);
    cudaGetSymbolAddress((void**)&p_v, g_v);
    cudaGetSymbolAddress((void**)&p_g, g_gt);

    const size_t WSLOT = (size_t)CDIM * CDIM;
    const int GEMM_SMEM = 3 * 32768;   // 98304 -> 2 CTAs/SM

    cudaFuncSetAttribute(k_gemm4, cudaFuncAttributeMaxDynamicSharedMemorySize, GEMM_SMEM);
    cudaFuncSetAttribute(k_gemm1, cudaFuncAttributeMaxDynamicSharedMemorySize, GEMM_SMEM);

    // fork s2 from main stream, run weight packing there
    cudaEventRecord(g_env.evRoot, 0);
    cudaStreamWaitEvent(g_env.s2, g_env.evRoot, 0);
    dim3 pg(16384, 5);
    k_packB_all<<<pg, 256, 0, g_env.s2>>>(w_r, w_k, w_v, w_g, w_o, p_wpack);
    cudaEventRecord(g_env.ePack, g_env.s2);

    // main: t5 -> lerp5
    k_prep_t5<<<MTOT / 64, 256>>>(x, maa_x, w1);
    k_lerp5<<<(MTOT / 16) * 8, 256>>>(x, w2, maa_w, maa_k, maa_v, maa_r, maa_g);

    // fork s1 after lerp5: decay chain (independent of gemm4)
    cudaEventRecord(g_env.eLerp, 0);
    cudaStreamWaitEvent(g_env.s1, g_env.eLerp, 0);
    k_decay_h<<<MTOT / 64, 256, 0, g_env.s1>>>(dw1);
    k_decay_w<<<(MTOT / 16) * 8, 256, 0, g_env.s1>>>(dw2, tdec);
    cudaEventRecord(g_env.eDecay, g_env.s1);

    // main: join packB, run the big fused GEMM
    cudaStreamWaitEvent(0, g_env.ePack, 0);
    dim3 gg4(CDIM / 128, MTOT / 128, 4);
    k_gemm4<<<gg4, 128, GEMM_SMEM>>>(p_apack, p_wpack, p_r, p_k, p_v, p_g);

    // main: join decay chain, then scan -> gn -> output proj
    cudaStreamWaitEvent(0, g_env.eDecay, 0);
    k_wkv<<<BB * HHEADS, 256>>>(u);

    k_gnmul<<<MTOT, 1024>>>(lnw, lnb);

    dim3 gg(CDIM / 128, MTOT / 128);
    k_gemm1<<<gg, 128, GEMM_SMEM>>>(p_ypack, p_wpack + 4 * WSLOT, out);
}